// round 11
// baseline (speedup 1.0000x reference)
#include <cuda_runtime.h>
#include <cuda_bf16.h>
#include <math.h>

#define BB 16
#define HH 256
#define WW 256
#define CC 64
#define M2K 12
#define NKY 24
#define FCH 128

// ---------------- device-global scratch ----------------
__device__ float    g_hA [(size_t)BB*CC*HH*WW];   // fp32 h (final layer only)
__device__ unsigned g_hPA[(size_t)BB*CC*HH*WW];   // split-packed h ping
__device__ unsigned g_hPB[(size_t)BB*CC*HH*WW];   // split-packed h pong
__device__ float2 g_xf[(size_t)BB*CC*NKY*M2K];
__device__ float2 g_yf[(size_t)BB*CC*NKY*M2K];
__device__ float2 g_g [(size_t)BB*CC*HH*M2K];
__device__ float2 g_wt[(size_t)4*NKY*M2K*CC*CC];
__device__ float2 g_tw[256];
__device__ unsigned g_E[256*24];    // fwd-W DFT matrix split-packed
__device__ unsigned g_EIc[24*256];  // inverse-W DFT matrix (alpha-scaled) split-packed [e][x]
__device__ unsigned g_pwp[4*CC*CC]; // split-packed pointwise weights [l][o][i]
__device__ unsigned g_w1p[CC*FCH];  // split-packed fc1 weights [c][d]

// ---------------- bf16 split-pack helpers ----------------
__device__ __forceinline__ unsigned split2(float a) {
    __nv_bfloat16 p = __float2bfloat16_rn(a);
    float pf = __bfloat162float(p);
    __nv_bfloat16 r = __float2bfloat16_rn(a - pf);
    return ((unsigned)__bfloat16_as_ushort(r) << 16) | (unsigned)__bfloat16_as_ushort(p);
}
__device__ __forceinline__ unsigned prmt(unsigned a, unsigned b, unsigned s) {
    unsigned d;
    asm("prmt.b32 %0, %1, %2, %3;" : "=r"(d) : "r"(a), "r"(b), "r"(s));
    return d;
}
__device__ __forceinline__ void mma_bf16(float d[4], unsigned a0, unsigned a1, unsigned b0) {
    asm volatile("mma.sync.aligned.m16n8k8.row.col.f32.bf16.bf16.f32 "
        "{%0,%1,%2,%3}, {%4,%5}, {%6}, {%0,%1,%2,%3};"
        : "+f"(d[0]), "+f"(d[1]), "+f"(d[2]), "+f"(d[3])
        : "r"(a0), "r"(a1), "r"(b0));
}
__device__ __forceinline__ void mma16(float d[4], unsigned a0, unsigned a1,
                                      unsigned a2, unsigned a3,
                                      unsigned b0, unsigned b1) {
    asm volatile("mma.sync.aligned.m16n8k16.row.col.f32.bf16.bf16.f32 "
        "{%0,%1,%2,%3}, {%4,%5,%6,%7}, {%8,%9}, {%0,%1,%2,%3};"
        : "+f"(d[0]), "+f"(d[1]), "+f"(d[2]), "+f"(d[3])
        : "r"(a0), "r"(a1), "r"(a2), "r"(a3), "r"(b0), "r"(b1));
}
__device__ __forceinline__ void cp_async16(unsigned smem_addr, const void* gptr) {
    asm volatile("cp.async.cg.shared.global [%0], [%1], 16;"
                 :: "r"(smem_addr), "l"(gptr));
}
// fast gelu: tanh-form with HW tanh.approx (err ~1e-4 rel vs exact-erf gelu)
__device__ __forceinline__ float gelu_f(float v) {
    float u = v * (0.7978845608f + 0.0356774081f * v * v);
    float t;
    asm("tanh.approx.f32 %0, %1;" : "=f"(t) : "f"(u));
    return 0.5f * v * (1.f + t);
}

// ---------------- twiddle tables ----------------
__global__ void k_tw() {
    int m = threadIdx.x;
    double s, c;
    sincospi((double)m / 128.0, &s, &c);
    g_tw[m]  = make_float2((float)c, (float)s);
}

__global__ void k_E() {
    int x = threadIdx.x;
#pragma unroll
    for (int j = 0; j < 12; j++) {
        double s, c;
        sincospi((double)((j * x) & 255) / 128.0, &s, &c);
        g_E[x*24 + 2*j    ] = split2((float)c);
        g_E[x*24 + 2*j + 1] = split2(-(float)s);
    }
    const float A1 = 1.f/65536.f, A2 = 2.f/65536.f;
#pragma unroll
    for (int e = 0; e < 24; e++) {
        double s, c;
        float v;
        if (e < 12) {
            sincospi((double)((e * x) & 255) / 128.0, &s, &c);
            v = ((e == 0) ? A1 : A2) * (float)c;
        } else {
            int j = e - 12;
            sincospi((double)((j * x) & 255) / 128.0, &s, &c);
            v = -A2 * (float)s;
        }
        g_EIc[e*256 + x] = split2(v);
    }
}

__global__ void k_pws(const float* __restrict__ pw) {
    int idx = blockIdx.x * 256 + threadIdx.x;
    g_pwp[idx] = split2(pw[idx]);
}
__global__ void k_w1p(const float* __restrict__ w1) {
    int idx = blockIdx.x * 256 + threadIdx.x;
    g_w1p[idx] = split2(w1[idx]);
}

// ---------------- spectral weight transpose ----------------
__global__ void k_wt(const float* __restrict__ scw) {
    size_t idx = (size_t)blockIdx.x * 256 + threadIdx.x;
    if (idx >= (size_t)4*2*CC*CC*144) return;
    size_t t = idx;
    int kx = t % 12; t /= 12;
    int ky = t % 12; t /= 12;
    int o  = t % CC; t /= CC;
    int i  = t % CC; t /= CC;
    int p  = t % 2;  t /= 2;
    int l  = (int)t;
    float re = scw[idx*2], im = scw[idx*2+1];
    int kyi = (p == 0) ? ky : (12 + ky);
    size_t dst = ((((size_t)l*NKY + kyi)*12 + kx)*CC + i)*CC + o;
    g_wt[dst] = make_float2(re, im);
}

// ---------------- lift: writes split-packed h ----------------
__global__ void k_lift(const float* __restrict__ x, const float* __restrict__ w,
                       const float* __restrict__ b) {
    size_t i4 = (size_t)blockIdx.x * 256 + threadIdx.x;
    int x4 = i4 & 63;
    int y  = (i4 >> 6) & 255;
    int c  = (i4 >> 14) & 63;
    int bb = (int)(i4 >> 20);
    float4 xv = ((const float4*)x)[((size_t)bb*256 + y)*64 + x4];
    float wc = w[c], bc = b[c];
    uint4 o;
    o.x = split2(xv.x*wc + bc); o.y = split2(xv.y*wc + bc);
    o.z = split2(xv.z*wc + bc); o.w = split2(xv.w*wc + bc);
    ((uint4*)g_hPA)[i4] = o;
}

// ---------------- fused forward: W-DFT GEMM (cp.async pipelined, k16 mma) + H-DFT ----------------
#define EST 28
#define AST 36
#define OFF_A0 7168
#define OFF_A1 16384
__global__ void __launch_bounds__(256) k_fwd(int l) {
    const unsigned* hin = (l & 1) ? g_hPB : g_hPA;
    __shared__ __align__(16) unsigned s_pool[25600];   // sE | sA0 | sA1  (100 KB)
    unsigned* sE = s_pool;
    int tid = threadIdx.x;
    int bc = blockIdx.x;
    const unsigned* hbase = hin + ((size_t)bc << 16);

    for (int t = tid; t < 256*24; t += 256)
        sE[(t/24)*EST + (t%24)] = g_E[t];

    {
        unsigned* sA = s_pool + OFF_A0;
#pragma unroll
        for (int it = 0; it < 8; it++) {
            int idx = it*256 + tid;
            int r = idx >> 3, q = idx & 7;
            cp_async16((unsigned)__cvta_generic_to_shared(&sA[r*AST + q*4]),
                       hbase + (r << 8) + q*4);
        }
        asm volatile("cp.async.commit_group;");
    }

    int wid = tid >> 5, lane = tid & 31, g = lane >> 2, t4 = lane & 3;
    float d[2][3][4];
#pragma unroll
    for (int mt = 0; mt < 2; mt++)
#pragma unroll
        for (int nt = 0; nt < 3; nt++)
#pragma unroll
            for (int r = 0; r < 4; r++) d[mt][nt][r] = 0.f;

#pragma unroll 1
    for (int xc = 0; xc < 8; xc++) {
        unsigned* sA = s_pool + ((xc & 1) ? OFF_A1 : OFF_A0);
        if (xc < 7) {
            unsigned* sN = s_pool + ((xc & 1) ? OFF_A0 : OFF_A1);
            int xn = (xc + 1) * 32;
#pragma unroll
            for (int it = 0; it < 8; it++) {
                int idx = it*256 + tid;
                int r = idx >> 3, q = idx & 7;
                cp_async16((unsigned)__cvta_generic_to_shared(&sN[r*AST + q*4]),
                           hbase + (r << 8) + xn + q*4);
            }
            asm volatile("cp.async.commit_group;");
            asm volatile("cp.async.wait_group 1;");
        } else {
            asm volatile("cp.async.wait_group 0;");
        }
        __syncthreads();

#pragma unroll
        for (int kk = 0; kk < 2; kk++) {
            int ko = kk*16 + 2*t4;
            int gx = xc*32 + ko;
            unsigned ap[2][4], ar[2][4];
#pragma unroll
            for (int mt = 0; mt < 2; mt++) {
                int r0 = wid*32 + mt*16 + g;
                uint2 L00 = *(const uint2*)&sA[ r0     *AST + ko];
                uint2 L08 = *(const uint2*)&sA[ r0     *AST + ko + 8];
                uint2 L10 = *(const uint2*)&sA[(r0 + 8)*AST + ko];
                uint2 L18 = *(const uint2*)&sA[(r0 + 8)*AST + ko + 8];
                ap[mt][0] = prmt(L00.x, L00.y, 0x5410u); ar[mt][0] = prmt(L00.x, L00.y, 0x7632u);
                ap[mt][1] = prmt(L10.x, L10.y, 0x5410u); ar[mt][1] = prmt(L10.x, L10.y, 0x7632u);
                ap[mt][2] = prmt(L08.x, L08.y, 0x5410u); ar[mt][2] = prmt(L08.x, L08.y, 0x7632u);
                ap[mt][3] = prmt(L18.x, L18.y, 0x5410u); ar[mt][3] = prmt(L18.x, L18.y, 0x7632u);
            }
#pragma unroll
            for (int nt = 0; nt < 3; nt++) {
                int n = nt*8 + g;
                unsigned w0 = sE[ gx     *EST + n];
                unsigned w1 = sE[(gx + 1)*EST + n];
                unsigned w8 = sE[(gx + 8)*EST + n];
                unsigned w9 = sE[(gx + 9)*EST + n];
                unsigned bp0 = prmt(w0, w1, 0x5410u), br0 = prmt(w0, w1, 0x7632u);
                unsigned bp1 = prmt(w8, w9, 0x5410u), br1 = prmt(w8, w9, 0x7632u);
#pragma unroll
                for (int mt = 0; mt < 2; mt++) {
                    mma16(d[mt][nt], ap[mt][0], ap[mt][1], ap[mt][2], ap[mt][3], bp0, bp1);
                    mma16(d[mt][nt], ap[mt][0], ap[mt][1], ap[mt][2], ap[mt][3], br0, br1);
                    mma16(d[mt][nt], ar[mt][0], ar[mt][1], ar[mt][2], ar[mt][3], bp0, bp1);
                }
            }
        }
        __syncthreads();
    }

    // phase 2: Xw -> smem, H-DFT, write g_xf
    float2* sXw = (float2*)(s_pool + OFF_A0);    // [y][kx] stride 13
    float2* stw = (float2*)(s_pool + OFF_A1);
#pragma unroll
    for (int mt = 0; mt < 2; mt++) {
        int r0 = wid*32 + mt*16 + g;
#pragma unroll
        for (int nt = 0; nt < 3; nt++) {
            int kx = nt*4 + t4;
            sXw[ r0     *13 + kx] = make_float2(d[mt][nt][0], d[mt][nt][1]);
            sXw[(r0 + 8)*13 + kx] = make_float2(d[mt][nt][2], d[mt][nt][3]);
        }
    }
    stw[tid] = g_tw[tid];
    __syncthreads();

    for (int cell = tid; cell < 288; cell += 256) {
        int kyi = cell / 12, kx = cell % 12;
        int ky  = (kyi < 12) ? kyi : (kyi + 232);
        float ar2 = 0.f, ai2 = 0.f;
        for (int y = 0; y < 256; y++) {
            float2 a = sXw[y*13 + kx];
            float2 w = stw[(ky*y) & 255];
            ar2 += a.x*w.x + a.y*w.y;
            ai2 += a.y*w.x - a.x*w.y;
        }
        g_xf[(size_t)bc*288 + cell] = make_float2(ar2, ai2);
    }
}

// ---------------- mode mixing ----------------
__global__ void k_mix(int l) {
    __shared__ float2 sxf[4][64];
    int b = blockIdx.x / 72, grp = blockIdx.x % 72;
    int cell0 = grp * 4;
    {
        int c = threadIdx.x >> 6, i = threadIdx.x & 63;
        sxf[c][i] = g_xf[((size_t)b*CC + i)*288 + cell0 + c];
    }
    __syncthreads();
    int cc = threadIdx.x >> 6, o = threadIdx.x & 63;
    int cell = cell0 + cc;
    int kyi = cell / 12, kx = cell % 12;
    const float2* wp = g_wt + (((size_t)l*NKY + kyi)*12 + kx)*4096 + o;
    float ar = 0.f, ai = 0.f;
#pragma unroll 8
    for (int i = 0; i < 64; i++) {
        float2 a = sxf[cc][i];
        float2 w = wp[(size_t)i * 64];
        ar += a.x*w.x - a.y*w.y;
        ai += a.x*w.y + a.y*w.x;
    }
    g_yf[((size_t)b*CC + o)*288 + cell] = make_float2(ar, ai);
}

// ---------------- inverse H ----------------
__global__ void k_inv_h() {
    __shared__ float2 sy[288];
    __shared__ float2 tw[256];
    int bo = blockIdx.x;
    for (int t = threadIdx.x; t < 256; t += 256) tw[t] = g_tw[t];
    for (int t = threadIdx.x; t < 288; t += 256) sy[t] = g_yf[(size_t)bo*288 + t];
    __syncthreads();
    int y = threadIdx.x;
    float2 acc[12];
#pragma unroll
    for (int kx = 0; kx < 12; kx++) acc[kx] = make_float2(0.f, 0.f);
    for (int kyi = 0; kyi < 24; kyi++) {
        int ky = (kyi < 12) ? kyi : (kyi + 232);
        float2 w = tw[(ky*y) & 255];
#pragma unroll
        for (int kx = 0; kx < 12; kx++) {
            float2 a = sy[kyi*12 + kx];
            acc[kx].x += a.x*w.x - a.y*w.y;
            acc[kx].y += a.x*w.y + a.y*w.x;
        }
    }
#pragma unroll
    for (int kx = 0; kx < 12; kx++)
        g_g[((size_t)bo*256 + y)*12 + kx] = acc[kx];
}

// ---------------- fused combine: per-(b,y) block, uniform K=88, k16 mma ----------------
#define KP 88
#define XP 68
__global__ void __launch_bounds__(256) k_combine(const float* __restrict__ pw_b, int l) {
    const unsigned* hin = (l & 1) ? g_hPB : g_hPA;
    unsigned* hpout = (l & 1) ? g_hPA : g_hPB;
    __shared__ __align__(16) unsigned sA[64*KP];    // [o][k] k<64 W, 64+e G (cos|sin order)
    __shared__ __align__(16) unsigned sB[88*XP];    // rows 0-63 h, rows 64-87 EI slice
    __shared__ __align__(16) float    sD[64*XP];
    __shared__ float  sbias[64];

    int y = blockIdx.x & 255;
    int b = blockIdx.x >> 8;
    int tid = threadIdx.x;

#pragma unroll
    for (int it = 0; it < 4; it++) {
        int t = it*256 + tid;
        int o = t >> 4, q = t & 15;
        uint4 v = *(const uint4*)(g_pwp + (size_t)l*4096 + o*64 + q*4);
        *(uint4*)&sA[o*KP + q*4] = v;
    }
#pragma unroll
    for (int it = 0; it < 3; it++) {
        int t = it*256 + tid;
        if (t < 768) {
            int o = t / 12, j = t % 12;
            float2 gv = g_g[(((size_t)b*64 + o)*256 + y)*12 + j];
            sA[o*KP + 64 + j] = split2(gv.x);
            sA[o*KP + 76 + j] = split2(gv.y);
        }
    }
    if (tid < 64) sbias[tid] = pw_b[l*64 + tid];

    int wid = tid >> 5, lane = tid & 31;
    int mt = wid & 3, nh = wid >> 2;
    int g = lane >> 2, t4 = lane & 3;

    uint4 pf[4];
#pragma unroll
    for (int it = 0; it < 4; it++) {
        int t = it*256 + tid;
        int i = t >> 4, q = t & 15;
        pf[it] = *(const uint4*)(hin + ((((size_t)b*64 + i)*256 + y) << 8) + q*4);
    }

#pragma unroll 1
    for (int xc = 0; xc < 4; xc++) {
        int x0 = xc << 6;
#pragma unroll
        for (int it = 0; it < 4; it++) {
            int t = it*256 + tid;
            int i = t >> 4, q = t & 15;
            *(uint4*)&sB[i*XP + q*4] = pf[it];
        }
        // EI slice rows 64..87
        for (int t = tid; t < 384; t += 256) {
            int e = t >> 4, q = t & 15;
            *(uint4*)&sB[(64 + e)*XP + q*4] = *(const uint4*)(g_EIc + e*256 + x0 + q*4);
        }
        __syncthreads();
        if (xc < 3) {
#pragma unroll
            for (int it = 0; it < 4; it++) {
                int t = it*256 + tid;
                int i = t >> 4, q = t & 15;
                pf[it] = *(const uint4*)(hin + ((((size_t)b*64 + i)*256 + y) << 8) + x0 + 64 + q*4);
            }
        }

        float d[4][4];
#pragma unroll
        for (int nt = 0; nt < 4; nt++)
#pragma unroll
            for (int r = 0; r < 4; r++) d[nt][r] = 0.f;

        // uniform K=88: 5 k16 tiles + 1 k8 tail
#pragma unroll
        for (int kt = 0; kt < 5; kt++) {
            int kb = kt*16 + 2*t4;
            uint2 A00 = *(const uint2*)&sA[(mt*16 + g    )*KP + kb];
            uint2 A08 = *(const uint2*)&sA[(mt*16 + g    )*KP + kb + 8];
            uint2 A10 = *(const uint2*)&sA[(mt*16 + g + 8)*KP + kb];
            uint2 A18 = *(const uint2*)&sA[(mt*16 + g + 8)*KP + kb + 8];
            unsigned ap0 = prmt(A00.x, A00.y, 0x5410u), ar0 = prmt(A00.x, A00.y, 0x7632u);
            unsigned ap1 = prmt(A10.x, A10.y, 0x5410u), ar1 = prmt(A10.x, A10.y, 0x7632u);
            unsigned ap2 = prmt(A08.x, A08.y, 0x5410u), ar2 = prmt(A08.x, A08.y, 0x7632u);
            unsigned ap3 = prmt(A18.x, A18.y, 0x5410u), ar3 = prmt(A18.x, A18.y, 0x7632u);
#pragma unroll
            for (int nt = 0; nt < 4; nt++) {
                int xl = nh*32 + nt*8 + g;
                unsigned w00 = sB[(kb    )*XP + xl];
                unsigned w01 = sB[(kb + 1)*XP + xl];
                unsigned w08 = sB[(kb + 8)*XP + xl];
                unsigned w09 = sB[(kb + 9)*XP + xl];
                unsigned bp0 = prmt(w00, w01, 0x5410u), br0 = prmt(w00, w01, 0x7632u);
                unsigned bp1 = prmt(w08, w09, 0x5410u), br1 = prmt(w08, w09, 0x7632u);
                mma16(d[nt], ap0, ap1, ap2, ap3, bp0, bp1);
                mma16(d[nt], ap0, ap1, ap2, ap3, br0, br1);
                mma16(d[nt], ar0, ar1, ar2, ar3, bp0, bp1);
            }
        }
        {
            int kb = 80 + 2*t4;
            uint2 A0 = *(const uint2*)&sA[(mt*16 + g    )*KP + kb];
            uint2 A1 = *(const uint2*)&sA[(mt*16 + g + 8)*KP + kb];
            unsigned ap0 = prmt(A0.x, A0.y, 0x5410u), ar0 = prmt(A0.x, A0.y, 0x7632u);
            unsigned ap1 = prmt(A1.x, A1.y, 0x5410u), ar1 = prmt(A1.x, A1.y, 0x7632u);
#pragma unroll
            for (int nt = 0; nt < 4; nt++) {
                int xl = nh*32 + nt*8 + g;
                unsigned w0 = sB[(kb    )*XP + xl];
                unsigned w1 = sB[(kb + 1)*XP + xl];
                unsigned bp = prmt(w0, w1, 0x5410u), br = prmt(w0, w1, 0x7632u);
                mma_bf16(d[nt], ap0, ap1, bp);
                mma_bf16(d[nt], ap0, ap1, br);
                mma_bf16(d[nt], ar0, ar1, bp);
            }
        }

#pragma unroll
        for (int nt = 0; nt < 4; nt++) {
            int xl = nh*32 + nt*8 + 2*t4;
            int o0 = mt*16 + g;
            *(float2*)&sD[ o0      * XP + xl] = make_float2(d[nt][0], d[nt][1]);
            *(float2*)&sD[(o0 + 8) * XP + xl] = make_float2(d[nt][2], d[nt][3]);
        }
        __syncthreads();

#pragma unroll
        for (int it = 0; it < 4; it++) {
            int o  = it*16 + (tid >> 4);
            int x4 = tid & 15;
            float4 v = *(float4*)&sD[o*XP + x4*4];
            float bias = sbias[o];
            size_t base = ((((size_t)b*64 + o)*256 + y) << 8) + x0 + x4*4;
            if (l < 3) {
                uint4 up;
                up.x = split2(gelu_f(v.x + bias));
                up.y = split2(gelu_f(v.y + bias));
                up.z = split2(gelu_f(v.z + bias));
                up.w = split2(gelu_f(v.w + bias));
                *(uint4*)(hpout + base) = up;
            } else {
                v.x += bias; v.y += bias; v.z += bias; v.w += bias;
                *(float4*)(g_hA + base) = v;
            }
        }
        __syncthreads();
    }
}

// ---------------- final: tensor-core fc1 (k16) + fast gelu + fc2 ----------------
#define FS 132
__global__ void __launch_bounds__(256) k_final(const float* __restrict__ b1,
                        const float* __restrict__ w2, const float* __restrict__ b2,
                        float* __restrict__ out) {
    __shared__ __align__(16) unsigned sH[64*FS];   // [c][x] split-packed
    __shared__ __align__(16) unsigned sW[64*FS];   // [c][d] split-packed
    __shared__ float sb1[FCH];
    __shared__ float sw2[FCH];
    int xh = blockIdx.x & 1;
    int y  = (blockIdx.x >> 1) & 255;
    int b  = blockIdx.x >> 9;
    int tid = threadIdx.x;
    int x0 = xh << 7;

#pragma unroll
    for (int it = 0; it < 8; it++) {
        int t = it*256 + tid;
        int c = t >> 5, q = t & 31;
        float4 v = *(const float4*)(g_hA + ((((size_t)b*64 + c)*256 + y) << 8) + x0 + q*4);
        sH[c*FS + q*4 + 0] = split2(v.x);
        sH[c*FS + q*4 + 1] = split2(v.y);
        sH[c*FS + q*4 + 2] = split2(v.z);
        sH[c*FS + q*4 + 3] = split2(v.w);
    }
#pragma unroll
    for (int it = 0; it < 8; it++) {
        int t = it*256 + tid;
        int c = t >> 5, q = t & 31;
        uint4 v = *(const uint4*)(g_w1p + c*128 + q*4);
        *(uint4*)&sW[c*FS + q*4] = v;
    }
    if (tid < 128) { sb1[tid] = b1[tid]; sw2[tid] = w2[tid]; }
    __syncthreads();

    int wid = tid >> 5, lane = tid & 31;
    int g = lane >> 2, t4 = lane & 3;
    float d[16][4];
#pragma unroll
    for (int nt = 0; nt < 16; nt++)
#pragma unroll
        for (int r = 0; r < 4; r++) d[nt][r] = 0.f;

#pragma unroll
    for (int kt = 0; kt < 4; kt++) {
        int c0 = kt*16 + 2*t4;
        int X0 = wid*16 + g;
        unsigned a00 = sH[ c0     *FS + X0], a01 = sH[(c0 + 1)*FS + X0];
        unsigned a08 = sH[(c0 + 8)*FS + X0], a09 = sH[(c0 + 9)*FS + X0];
        unsigned a10 = sH[ c0     *FS + X0 + 8], a11 = sH[(c0 + 1)*FS + X0 + 8];
        unsigned a18 = sH[(c0 + 8)*FS + X0 + 8], a19 = sH[(c0 + 9)*FS + X0 + 8];
        unsigned ap0 = prmt(a00, a01, 0x5410u), ar0 = prmt(a00, a01, 0x7632u);
        unsigned ap1 = prmt(a10, a11, 0x5410u), ar1 = prmt(a10, a11, 0x7632u);
        unsigned ap2 = prmt(a08, a09, 0x5410u), ar2 = prmt(a08, a09, 0x7632u);
        unsigned ap3 = prmt(a18, a19, 0x5410u), ar3 = prmt(a18, a19, 0x7632u);
#pragma unroll
        for (int nt = 0; nt < 16; nt++) {
            int n = nt*8 + g;
            unsigned w00 = sW[ c0     *FS + n], w01 = sW[(c0 + 1)*FS + n];
            unsigned w08 = sW[(c0 + 8)*FS + n], w09 = sW[(c0 + 9)*FS + n];
            unsigned bp0 = prmt(w00, w01, 0x5410u), br0 = prmt(w00, w01, 0x7632u);
            unsigned bp1 = prmt(w08, w09, 0x5410u), br1 = prmt(w08, w09, 0x7632u);
            mma16(d[nt], ap0, ap1, ap2, ap3, bp0, bp1);
            mma16(d[nt], ap0, ap1, ap2, ap3, br0, br1);
            mma16(d[nt], ar0, ar1, ar2, ar3, bp0, bp1);
        }
    }

    float pA = 0.f, pB = 0.f;
#pragma unroll
    for (int nt = 0; nt < 16; nt++) {
        int d0 = nt*8 + 2*t4, d1 = d0 + 1;
        float bb0 = sb1[d0], bb1 = sb1[d1];
        float ww0 = sw2[d0], ww1 = sw2[d1];
        pA += gelu_f(d[nt][0] + bb0) * ww0;
        pA += gelu_f(d[nt][1] + bb1) * ww1;
        pB += gelu_f(d[nt][2] + bb0) * ww0;
        pB += gelu_f(d[nt][3] + bb1) * ww1;
    }
    pA += __shfl_xor_sync(0xffffffffu, pA, 1);
    pA += __shfl_xor_sync(0xffffffffu, pA, 2);
    pB += __shfl_xor_sync(0xffffffffu, pB, 1);
    pB += __shfl_xor_sync(0xffffffffu, pB, 2);
    if (t4 == 0) {
        float bias2 = b2[0];
        size_t base = ((size_t)b*256 + y)*256 + x0 + wid*16 + g;
        out[base    ] = pA + bias2;
        out[base + 8] = pB + bias2;
    }
}

// ---------------- launcher ----------------
extern "C" void kernel_launch(void* const* d_in, const int* in_sizes, int n_in,
                              void* d_out, int out_size) {
    const float* x     = (const float*)d_in[0];
    const float* fc0_w = (const float*)d_in[1];
    const float* fc0_b = (const float*)d_in[2];
    const float* sc_w  = (const float*)d_in[3];
    const float* pw_w  = (const float*)d_in[4];
    const float* pw_b  = (const float*)d_in[5];
    const float* fc1_w = (const float*)d_in[6];
    const float* fc1_b = (const float*)d_in[7];
    const float* fc2_w = (const float*)d_in[8];
    const float* fc2_b = (const float*)d_in[9];
    float* out = (float*)d_out;

    k_E<<<1, 256>>>();
    k_tw<<<1, 256>>>();
    k_lift<<<65536, 256>>>(x, fc0_w, fc0_b);
    k_fwd<<<1024, 256>>>(0);
    k_wt<<<18432, 256>>>(sc_w);
    k_pws<<<64, 256>>>(pw_w);
    k_w1p<<<32, 256>>>(fc1_w);
    k_mix<<<1152, 256>>>(0);
    k_inv_h<<<1024, 256>>>();
    k_combine<<<4096, 256>>>(pw_b, 0);
    for (int l = 1; l < 4; l++) {
        k_fwd<<<1024, 256>>>(l);
        k_mix<<<1152, 256>>>(l);
        k_inv_h<<<1024, 256>>>();
        k_combine<<<4096, 256>>>(pw_b, l);
    }
    k_final<<<8192, 256>>>(fc1_b, fc2_w, fc2_b, out);
}

// round 12
// speedup vs baseline: 1.2599x; 1.2599x over previous
#include <cuda_runtime.h>
#include <cuda_bf16.h>
#include <math.h>

#define BB 16
#define HH 256
#define WW 256
#define CC 64
#define M2K 12
#define NKY 24
#define FCH 128

// ---------------- device-global scratch ----------------
__device__ float    g_hA [(size_t)BB*CC*HH*WW];   // fp32 h (final layer only)
__device__ unsigned g_hPA[(size_t)BB*CC*HH*WW];   // split-packed h ping
__device__ unsigned g_hPB[(size_t)BB*CC*HH*WW];   // split-packed h pong
__device__ float2 g_xf[(size_t)BB*CC*NKY*M2K];
__device__ float2 g_yf[(size_t)BB*CC*NKY*M2K];
__device__ float2 g_g [(size_t)BB*CC*HH*M2K];
__device__ float2 g_wt[(size_t)4*NKY*M2K*CC*CC];
__device__ float2 g_tw[256];
__device__ unsigned g_twc[256];    // split-packed cos
__device__ unsigned g_tws[256];    // split-packed sin
__device__ unsigned g_E[256*24];   // fwd-W DFT matrix split-packed
__device__ unsigned g_pwp[4*CC*CC];// split-packed pointwise weights [l][o][i]
__device__ unsigned g_w1p[CC*FCH]; // split-packed fc1 weights [c][d]

// ---------------- bf16 split-pack helpers ----------------
__device__ __forceinline__ unsigned split2(float a) {
    __nv_bfloat16 p = __float2bfloat16_rn(a);
    float pf = __bfloat162float(p);
    __nv_bfloat16 r = __float2bfloat16_rn(a - pf);
    return ((unsigned)__bfloat16_as_ushort(r) << 16) | (unsigned)__bfloat16_as_ushort(p);
}
__device__ __forceinline__ unsigned prmt(unsigned a, unsigned b, unsigned s) {
    unsigned d;
    asm("prmt.b32 %0, %1, %2, %3;" : "=r"(d) : "r"(a), "r"(b), "r"(s));
    return d;
}
__device__ __forceinline__ unsigned mulbf2(unsigned a, unsigned b) {
    unsigned d;
    asm("mul.rn.bf16x2 %0, %1, %2;" : "=r"(d) : "r"(a), "r"(b));
    return d;
}
__device__ __forceinline__ unsigned packbf2(float lo, float hi) {
    unsigned l = (unsigned)__bfloat16_as_ushort(__float2bfloat16_rn(lo));
    unsigned h = (unsigned)__bfloat16_as_ushort(__float2bfloat16_rn(hi));
    return (h << 16) | l;
}
__device__ __forceinline__ void mma_bf16(float d[4], unsigned a0, unsigned a1, unsigned b0) {
    asm volatile("mma.sync.aligned.m16n8k8.row.col.f32.bf16.bf16.f32 "
        "{%0,%1,%2,%3}, {%4,%5}, {%6}, {%0,%1,%2,%3};"
        : "+f"(d[0]), "+f"(d[1]), "+f"(d[2]), "+f"(d[3])
        : "r"(a0), "r"(a1), "r"(b0));
}
__device__ __forceinline__ void mma16(float d[4], unsigned a0, unsigned a1,
                                      unsigned a2, unsigned a3,
                                      unsigned b0, unsigned b1) {
    asm volatile("mma.sync.aligned.m16n8k16.row.col.f32.bf16.bf16.f32 "
        "{%0,%1,%2,%3}, {%4,%5,%6,%7}, {%8,%9}, {%0,%1,%2,%3};"
        : "+f"(d[0]), "+f"(d[1]), "+f"(d[2]), "+f"(d[3])
        : "r"(a0), "r"(a1), "r"(a2), "r"(a3), "r"(b0), "r"(b1));
}
__device__ __forceinline__ void cp_async16(unsigned smem_addr, const void* gptr) {
    asm volatile("cp.async.cg.shared.global [%0], [%1], 16;"
                 :: "r"(smem_addr), "l"(gptr));
}

// ---------------- twiddle tables ----------------
__global__ void k_tw() {
    int m = threadIdx.x;
    double s, c;
    sincospi((double)m / 128.0, &s, &c);
    g_tw[m]  = make_float2((float)c, (float)s);
    g_twc[m] = split2((float)c);
    g_tws[m] = split2((float)s);
}

__global__ void k_E() {
    int x = threadIdx.x;
#pragma unroll
    for (int j = 0; j < 12; j++) {
        double s, c;
        sincospi((double)((j * x) & 255) / 128.0, &s, &c);
        g_E[x*24 + 2*j    ] = split2((float)c);
        g_E[x*24 + 2*j + 1] = split2(-(float)s);
    }
}

__global__ void k_pws(const float* __restrict__ pw) {
    int idx = blockIdx.x * 256 + threadIdx.x;
    g_pwp[idx] = split2(pw[idx]);
}
__global__ void k_w1p(const float* __restrict__ w1) {
    int idx = blockIdx.x * 256 + threadIdx.x;
    g_w1p[idx] = split2(w1[idx]);
}

// ---------------- spectral weight transpose ----------------
__global__ void k_wt(const float* __restrict__ scw) {
    size_t idx = (size_t)blockIdx.x * 256 + threadIdx.x;
    if (idx >= (size_t)4*2*CC*CC*144) return;
    size_t t = idx;
    int kx = t % 12; t /= 12;
    int ky = t % 12; t /= 12;
    int o  = t % CC; t /= CC;
    int i  = t % CC; t /= CC;
    int p  = t % 2;  t /= 2;
    int l  = (int)t;
    float re = scw[idx*2], im = scw[idx*2+1];
    int kyi = (p == 0) ? ky : (12 + ky);
    size_t dst = ((((size_t)l*NKY + kyi)*12 + kx)*CC + i)*CC + o;
    g_wt[dst] = make_float2(re, im);
}

// ---------------- lift: writes split-packed h ----------------
__global__ void k_lift(const float* __restrict__ x, const float* __restrict__ w,
                       const float* __restrict__ b) {
    size_t i4 = (size_t)blockIdx.x * 256 + threadIdx.x;
    int x4 = i4 & 63;
    int y  = (i4 >> 6) & 255;
    int c  = (i4 >> 14) & 63;
    int bb = (int)(i4 >> 20);
    float4 xv = ((const float4*)x)[((size_t)bb*256 + y)*64 + x4];
    float wc = w[c], bc = b[c];
    uint4 o;
    o.x = split2(xv.x*wc + bc); o.y = split2(xv.y*wc + bc);
    o.z = split2(xv.z*wc + bc); o.w = split2(xv.w*wc + bc);
    ((uint4*)g_hPA)[i4] = o;
}

// ---------------- fused forward: W-DFT GEMM + H-DFT, 16-col chunks, 3 CTA/SM ----------------
#define EST 28
#define BST 20
#define OFF_B0 7168
#define OFF_B1 12288
__global__ void __launch_bounds__(256, 3) k_fwd(int l) {
    const unsigned* hin = (l & 1) ? g_hPB : g_hPA;
    __shared__ __align__(16) unsigned s_pool[17408];   // sE(28672B) | buf0(20480B) | buf1(20480B)
    unsigned* sE = s_pool;
    int tid = threadIdx.x;
    int bc = blockIdx.x;
    const unsigned* hbase = hin + ((size_t)bc << 16);

    for (int t = tid; t < 256*24; t += 256)
        sE[(t/24)*EST + (t%24)] = g_E[t];

    // issue chunk 0 (16 columns, 256 rows)
    {
        unsigned* sB = s_pool + OFF_B0;
#pragma unroll
        for (int it = 0; it < 4; it++) {
            int idx = it*256 + tid;
            int r = idx >> 2, q = idx & 3;
            cp_async16((unsigned)__cvta_generic_to_shared(&sB[r*BST + q*4]),
                       hbase + (r << 8) + q*4);
        }
        asm volatile("cp.async.commit_group;");
    }

    int wid = tid >> 5, lane = tid & 31, g = lane >> 2, t4 = lane & 3;
    float d[2][3][4];
#pragma unroll
    for (int mt = 0; mt < 2; mt++)
#pragma unroll
        for (int nt = 0; nt < 3; nt++)
#pragma unroll
            for (int r = 0; r < 4; r++) d[mt][nt][r] = 0.f;

#pragma unroll 1
    for (int xc = 0; xc < 16; xc++) {
        unsigned* sB = s_pool + ((xc & 1) ? OFF_B1 : OFF_B0);
        if (xc < 15) {
            unsigned* sN = s_pool + ((xc & 1) ? OFF_B0 : OFF_B1);
            int xn = (xc + 1) * 16;
#pragma unroll
            for (int it = 0; it < 4; it++) {
                int idx = it*256 + tid;
                int r = idx >> 2, q = idx & 3;
                cp_async16((unsigned)__cvta_generic_to_shared(&sN[r*BST + q*4]),
                           hbase + (r << 8) + xn + q*4);
            }
            asm volatile("cp.async.commit_group;");
            asm volatile("cp.async.wait_group 1;");
        } else {
            asm volatile("cp.async.wait_group 0;");
        }
        __syncthreads();

        {
            int ko = 2*t4;
            int gx = xc*16 + ko;
            unsigned ap[2][4], ar[2][4];
#pragma unroll
            for (int mt = 0; mt < 2; mt++) {
                int r0 = wid*32 + mt*16 + g;
                uint2 L00 = *(const uint2*)&sB[ r0     *BST + ko];
                uint2 L08 = *(const uint2*)&sB[ r0     *BST + ko + 8];
                uint2 L10 = *(const uint2*)&sB[(r0 + 8)*BST + ko];
                uint2 L18 = *(const uint2*)&sB[(r0 + 8)*BST + ko + 8];
                ap[mt][0] = prmt(L00.x, L00.y, 0x5410u); ar[mt][0] = prmt(L00.x, L00.y, 0x7632u);
                ap[mt][1] = prmt(L10.x, L10.y, 0x5410u); ar[mt][1] = prmt(L10.x, L10.y, 0x7632u);
                ap[mt][2] = prmt(L08.x, L08.y, 0x5410u); ar[mt][2] = prmt(L08.x, L08.y, 0x7632u);
                ap[mt][3] = prmt(L18.x, L18.y, 0x5410u); ar[mt][3] = prmt(L18.x, L18.y, 0x7632u);
            }
#pragma unroll
            for (int nt = 0; nt < 3; nt++) {
                int n = nt*8 + g;
                unsigned w0 = sE[ gx     *EST + n];
                unsigned w1 = sE[(gx + 1)*EST + n];
                unsigned w8 = sE[(gx + 8)*EST + n];
                unsigned w9 = sE[(gx + 9)*EST + n];
                unsigned bp0 = prmt(w0, w1, 0x5410u), br0 = prmt(w0, w1, 0x7632u);
                unsigned bp1 = prmt(w8, w9, 0x5410u), br1 = prmt(w8, w9, 0x7632u);
#pragma unroll
                for (int mt = 0; mt < 2; mt++) {
                    mma16(d[mt][nt], ap[mt][0], ap[mt][1], ap[mt][2], ap[mt][3], bp0, bp1);
                    mma16(d[mt][nt], ap[mt][0], ap[mt][1], ap[mt][2], ap[mt][3], br0, br1);
                    mma16(d[mt][nt], ar[mt][0], ar[mt][1], ar[mt][2], ar[mt][3], bp0, bp1);
                }
            }
        }
        __syncthreads();
    }

    // phase 2: Xw -> smem, H-DFT, write g_xf
    float2* sXw = (float2*)(s_pool + OFF_B0);    // [y][kx] stride 13 (6656 words)
    float2* stw = (float2*)(s_pool + 13824);     // 512 words
#pragma unroll
    for (int mt = 0; mt < 2; mt++) {
        int r0 = wid*32 + mt*16 + g;
#pragma unroll
        for (int nt = 0; nt < 3; nt++) {
            int kx = nt*4 + t4;
            sXw[ r0     *13 + kx] = make_float2(d[mt][nt][0], d[mt][nt][1]);
            sXw[(r0 + 8)*13 + kx] = make_float2(d[mt][nt][2], d[mt][nt][3]);
        }
    }
    stw[tid] = g_tw[tid];
    __syncthreads();

    for (int cell = tid; cell < 288; cell += 256) {
        int kyi = cell / 12, kx = cell % 12;
        int ky  = (kyi < 12) ? kyi : (kyi + 232);
        float ar2 = 0.f, ai2 = 0.f;
        for (int y = 0; y < 256; y++) {
            float2 a = sXw[y*13 + kx];
            float2 w = stw[(ky*y) & 255];
            ar2 += a.x*w.x + a.y*w.y;
            ai2 += a.y*w.x - a.x*w.y;
        }
        g_xf[(size_t)bc*288 + cell] = make_float2(ar2, ai2);
    }
}

// ---------------- mode mixing ----------------
__global__ void k_mix(int l) {
    __shared__ float2 sxf[4][64];
    int b = blockIdx.x / 72, grp = blockIdx.x % 72;
    int cell0 = grp * 4;
    {
        int c = threadIdx.x >> 6, i = threadIdx.x & 63;
        sxf[c][i] = g_xf[((size_t)b*CC + i)*288 + cell0 + c];
    }
    __syncthreads();
    int cc = threadIdx.x >> 6, o = threadIdx.x & 63;
    int cell = cell0 + cc;
    int kyi = cell / 12, kx = cell % 12;
    const float2* wp = g_wt + (((size_t)l*NKY + kyi)*12 + kx)*4096 + o;
    float ar = 0.f, ai = 0.f;
#pragma unroll 8
    for (int i = 0; i < 64; i++) {
        float2 a = sxf[cc][i];
        float2 w = wp[(size_t)i * 64];
        ar += a.x*w.x - a.y*w.y;
        ai += a.x*w.y + a.y*w.x;
    }
    g_yf[((size_t)b*CC + o)*288 + cell] = make_float2(ar, ai);
}

// ---------------- inverse H ----------------
__global__ void k_inv_h() {
    __shared__ float2 sy[288];
    __shared__ float2 tw[256];
    int bo = blockIdx.x;
    for (int t = threadIdx.x; t < 256; t += 256) tw[t] = g_tw[t];
    for (int t = threadIdx.x; t < 288; t += 256) sy[t] = g_yf[(size_t)bo*288 + t];
    __syncthreads();
    int y = threadIdx.x;
    float2 acc[12];
#pragma unroll
    for (int kx = 0; kx < 12; kx++) acc[kx] = make_float2(0.f, 0.f);
    for (int kyi = 0; kyi < 24; kyi++) {
        int ky = (kyi < 12) ? kyi : (kyi + 232);
        float2 w = tw[(ky*y) & 255];
#pragma unroll
        for (int kx = 0; kx < 12; kx++) {
            float2 a = sy[kyi*12 + kx];
            acc[kx].x += a.x*w.x - a.y*w.y;
            acc[kx].y += a.x*w.y + a.y*w.x;
        }
    }
#pragma unroll
    for (int kx = 0; kx < 12; kx++)
        g_g[((size_t)bo*256 + y)*12 + kx] = acc[kx];
}

// ---------------- fused combine: per-(b,y) block, 4 x-chunks, k16 mma ----------------
#define KP 88
#define XP 68
__global__ void __launch_bounds__(256) k_combine(const float* __restrict__ pw_b, int l) {
    const unsigned* hin = (l & 1) ? g_hPB : g_hPA;
    unsigned* hpout = (l & 1) ? g_hPA : g_hPB;
    __shared__ __align__(16) unsigned sA[64*KP];
    __shared__ __align__(16) unsigned sB[64*XP];
    __shared__ __align__(16) float    sD[64*XP];
    __shared__ unsigned s_twc[256];
    __shared__ unsigned s_tws[256];
    __shared__ float  sbias[64];

    int y = blockIdx.x & 255;
    int b = blockIdx.x >> 8;
    int tid = threadIdx.x;

#pragma unroll
    for (int it = 0; it < 4; it++) {
        int t = it*256 + tid;
        int o = t >> 4, q = t & 15;
        uint4 v = *(const uint4*)(g_pwp + (size_t)l*4096 + o*64 + q*4);
        *(uint4*)&sA[o*KP + q*4] = v;
    }
#pragma unroll
    for (int it = 0; it < 3; it++) {
        int t = it*256 + tid;
        if (t < 768) {
            int o = t / 12, j = t % 12;
            float2 gv = g_g[(((size_t)b*64 + o)*256 + y)*12 + j];
            sA[o*KP + 64 + j] = split2(gv.x);
            sA[o*KP + 76 + j] = split2(gv.y);
        }
    }
    s_twc[tid & 255] = g_twc[tid & 255];
    s_tws[tid & 255] = g_tws[tid & 255];
    if (tid < 64) sbias[tid] = pw_b[l*64 + tid];

    int wid = tid >> 5, lane = tid & 31;
    int mt = wid & 3, nh = wid >> 2;
    int g = lane >> 2, t4 = lane & 3;
    const float A1 = 1.f/65536.f, A2 = 2.f/65536.f;

    uint4 pf[4];
#pragma unroll
    for (int it = 0; it < 4; it++) {
        int t = it*256 + tid;
        int i = t >> 4, q = t & 15;
        pf[it] = *(const uint4*)(hin + ((((size_t)b*64 + i)*256 + y) << 8) + q*4);
    }

#pragma unroll 1
    for (int xc = 0; xc < 4; xc++) {
        int x0 = xc << 6;
#pragma unroll
        for (int it = 0; it < 4; it++) {
            int t = it*256 + tid;
            int i = t >> 4, q = t & 15;
            *(uint4*)&sB[i*XP + q*4] = pf[it];
        }
        __syncthreads();
        if (xc < 3) {
#pragma unroll
            for (int it = 0; it < 4; it++) {
                int t = it*256 + tid;
                int i = t >> 4, q = t & 15;
                pf[it] = *(const uint4*)(hin + ((((size_t)b*64 + i)*256 + y) << 8) + x0 + 64 + q*4);
            }
        }

        float d[4][4];
#pragma unroll
        for (int nt = 0; nt < 4; nt++)
#pragma unroll
            for (int r = 0; r < 4; r++) d[nt][r] = 0.f;

        // K=64 pointwise weights: 4 k16 tiles
#pragma unroll
        for (int kt = 0; kt < 4; kt++) {
            int kb = kt*16 + 2*t4;
            uint2 A00 = *(const uint2*)&sA[(mt*16 + g    )*KP + kb];
            uint2 A08 = *(const uint2*)&sA[(mt*16 + g    )*KP + kb + 8];
            uint2 A10 = *(const uint2*)&sA[(mt*16 + g + 8)*KP + kb];
            uint2 A18 = *(const uint2*)&sA[(mt*16 + g + 8)*KP + kb + 8];
            unsigned ap0 = prmt(A00.x, A00.y, 0x5410u), ar0 = prmt(A00.x, A00.y, 0x7632u);
            unsigned ap1 = prmt(A10.x, A10.y, 0x5410u), ar1 = prmt(A10.x, A10.y, 0x7632u);
            unsigned ap2 = prmt(A08.x, A08.y, 0x5410u), ar2 = prmt(A08.x, A08.y, 0x7632u);
            unsigned ap3 = prmt(A18.x, A18.y, 0x5410u), ar3 = prmt(A18.x, A18.y, 0x7632u);
#pragma unroll
            for (int nt = 0; nt < 4; nt++) {
                int xl = nh*32 + nt*8 + g;
                unsigned w00 = sB[(kb    )*XP + xl];
                unsigned w01 = sB[(kb + 1)*XP + xl];
                unsigned w08 = sB[(kb + 8)*XP + xl];
                unsigned w09 = sB[(kb + 9)*XP + xl];
                unsigned bp0 = prmt(w00, w01, 0x5410u), br0 = prmt(w00, w01, 0x7632u);
                unsigned bp1 = prmt(w08, w09, 0x5410u), br1 = prmt(w08, w09, 0x7632u);
                mma16(d[nt], ap0, ap1, ap2, ap3, bp0, bp1);
                mma16(d[nt], ap0, ap1, ap2, ap3, br0, br1);
                mma16(d[nt], ar0, ar1, ar2, ar3, bp0, bp1);
            }
        }

        // spectral K=24: one k16 tile (e 0..15) + one k8 tile (e 16..23)
        {
            int e0 = 2*t4;
            int e1 = 2*t4 + 8;
            uint2 A00 = *(const uint2*)&sA[(mt*16 + g    )*KP + 64 + e0];
            uint2 A08 = *(const uint2*)&sA[(mt*16 + g    )*KP + 64 + e0 + 8];
            uint2 A10 = *(const uint2*)&sA[(mt*16 + g + 8)*KP + 64 + e0];
            uint2 A18 = *(const uint2*)&sA[(mt*16 + g + 8)*KP + 64 + e0 + 8];
            unsigned ap0 = prmt(A00.x, A00.y, 0x5410u), ar0 = prmt(A00.x, A00.y, 0x7632u);
            unsigned ap1 = prmt(A10.x, A10.y, 0x5410u), ar1 = prmt(A10.x, A10.y, 0x7632u);
            unsigned ap2 = prmt(A08.x, A08.y, 0x5410u), ar2 = prmt(A08.x, A08.y, 0x7632u);
            unsigned ap3 = prmt(A18.x, A18.y, 0x5410u), ar3 = prmt(A18.x, A18.y, 0x7632u);
            unsigned alpha0 = packbf2((e0 == 0) ? A1 : A2, A2);
            bool sin1 = (e1 >= 12);
            const unsigned* tab1 = sin1 ? s_tws : s_twc;
            int j1 = sin1 ? (e1 - 12) : e1;
            unsigned alpha1 = sin1 ? packbf2(-A2, -A2) : packbf2(A2, A2);
#pragma unroll
            for (int nt = 0; nt < 4; nt++) {
                int xl = nh*32 + nt*8 + g;
                int xg = x0 + xl;
                unsigned w00 = s_twc[( e0     *xg) & 255];
                unsigned w01 = s_twc[((e0 + 1)*xg) & 255];
                unsigned w10 = tab1[( j1     *xg) & 255];
                unsigned w11 = tab1[((j1 + 1)*xg) & 255];
                unsigned bp0 = mulbf2(prmt(w00, w01, 0x5410u), alpha0);
                unsigned br0 = mulbf2(prmt(w00, w01, 0x7632u), alpha0);
                unsigned bp1 = mulbf2(prmt(w10, w11, 0x5410u), alpha1);
                unsigned br1 = mulbf2(prmt(w10, w11, 0x7632u), alpha1);
                mma16(d[nt], ap0, ap1, ap2, ap3, bp0, bp1);
                mma16(d[nt], ap0, ap1, ap2, ap3, br0, br1);
                mma16(d[nt], ar0, ar1, ar2, ar3, bp0, bp1);
            }
        }
        {
            uint2 A0 = *(const uint2*)&sA[(mt*16 + g    )*KP + 80 + 2*t4];
            uint2 A1r = *(const uint2*)&sA[(mt*16 + g + 8)*KP + 80 + 2*t4];
            unsigned ap0 = prmt(A0.x,  A0.y,  0x5410u), ar0 = prmt(A0.x,  A0.y,  0x7632u);
            unsigned ap1 = prmt(A1r.x, A1r.y, 0x5410u), ar1 = prmt(A1r.x, A1r.y, 0x7632u);
            int j = 4 + 2*t4;
            unsigned alpha = packbf2(-A2, -A2);
#pragma unroll
            for (int nt = 0; nt < 4; nt++) {
                int xl = nh*32 + nt*8 + g;
                int xg = x0 + xl;
                unsigned w0 = s_tws[( j     *xg) & 255];
                unsigned w1 = s_tws[((j + 1)*xg) & 255];
                unsigned bp = mulbf2(prmt(w0, w1, 0x5410u), alpha);
                unsigned br = mulbf2(prmt(w0, w1, 0x7632u), alpha);
                mma_bf16(d[nt], ap0, ap1, bp);
                mma_bf16(d[nt], ap0, ap1, br);
                mma_bf16(d[nt], ar0, ar1, bp);
            }
        }

#pragma unroll
        for (int nt = 0; nt < 4; nt++) {
            int xl = nh*32 + nt*8 + 2*t4;
            int o0 = mt*16 + g;
            *(float2*)&sD[ o0      * XP + xl] = make_float2(d[nt][0], d[nt][1]);
            *(float2*)&sD[(o0 + 8) * XP + xl] = make_float2(d[nt][2], d[nt][3]);
        }
        __syncthreads();

#pragma unroll
        for (int it = 0; it < 4; it++) {
            int o  = it*16 + (tid >> 4);
            int x4 = tid & 15;
            float4 v = *(float4*)&sD[o*XP + x4*4];
            float bias = sbias[o];
            size_t base = ((((size_t)b*64 + o)*256 + y) << 8) + x0 + x4*4;
            if (l < 3) {
                float u0 = v.x + bias, u1 = v.y + bias, u2 = v.z + bias, u3 = v.w + bias;
                u0 = 0.5f*u0*(1.f + erff(u0*0.70710678118654752f));
                u1 = 0.5f*u1*(1.f + erff(u1*0.70710678118654752f));
                u2 = 0.5f*u2*(1.f + erff(u2*0.70710678118654752f));
                u3 = 0.5f*u3*(1.f + erff(u3*0.70710678118654752f));
                uint4 up;
                up.x = split2(u0); up.y = split2(u1); up.z = split2(u2); up.w = split2(u3);
                *(uint4*)(hpout + base) = up;
            } else {
                v.x += bias; v.y += bias; v.z += bias; v.w += bias;
                *(float4*)(g_hA + base) = v;
            }
        }
        __syncthreads();
    }
}

// ---------------- final: tensor-core fc1 (k16) + gelu + fc2 ----------------
#define FS 132
__global__ void __launch_bounds__(256) k_final(const float* __restrict__ b1,
                        const float* __restrict__ w2, const float* __restrict__ b2,
                        float* __restrict__ out) {
    __shared__ __align__(16) unsigned sH[64*FS];   // [c][x] split-packed
    __shared__ __align__(16) unsigned sW[64*FS];   // [c][d] split-packed
    __shared__ float sb1[FCH];
    __shared__ float sw2[FCH];
    int xh = blockIdx.x & 1;
    int y  = (blockIdx.x >> 1) & 255;
    int b  = blockIdx.x >> 9;
    int tid = threadIdx.x;
    int x0 = xh << 7;

#pragma unroll
    for (int it = 0; it < 8; it++) {
        int t = it*256 + tid;
        int c = t >> 5, q = t & 31;
        float4 v = *(const float4*)(g_hA + ((((size_t)b*64 + c)*256 + y) << 8) + x0 + q*4);
        sH[c*FS + q*4 + 0] = split2(v.x);
        sH[c*FS + q*4 + 1] = split2(v.y);
        sH[c*FS + q*4 + 2] = split2(v.z);
        sH[c*FS + q*4 + 3] = split2(v.w);
    }
#pragma unroll
    for (int it = 0; it < 8; it++) {
        int t = it*256 + tid;
        int c = t >> 5, q = t & 31;
        uint4 v = *(const uint4*)(g_w1p + c*128 + q*4);
        *(uint4*)&sW[c*FS + q*4] = v;
    }
    if (tid < 128) { sb1[tid] = b1[tid]; sw2[tid] = w2[tid]; }
    __syncthreads();

    int wid = tid >> 5, lane = tid & 31;
    int g = lane >> 2, t4 = lane & 3;
    float d[16][4];
#pragma unroll
    for (int nt = 0; nt < 16; nt++)
#pragma unroll
        for (int r = 0; r < 4; r++) d[nt][r] = 0.f;

#pragma unroll
    for (int kt = 0; kt < 4; kt++) {
        int c0 = kt*16 + 2*t4;
        int X0 = wid*16 + g;
        unsigned a00 = sH[ c0     *FS + X0], a01 = sH[(c0 + 1)*FS + X0];
        unsigned a08 = sH[(c0 + 8)*FS + X0], a09 = sH[(c0 + 9)*FS + X0];
        unsigned a10 = sH[ c0     *FS + X0 + 8], a11 = sH[(c0 + 1)*FS + X0 + 8];
        unsigned a18 = sH[(c0 + 8)*FS + X0 + 8], a19 = sH[(c0 + 9)*FS + X0 + 8];
        unsigned ap0 = prmt(a00, a01, 0x5410u), ar0 = prmt(a00, a01, 0x7632u);
        unsigned ap1 = prmt(a10, a11, 0x5410u), ar1 = prmt(a10, a11, 0x7632u);
        unsigned ap2 = prmt(a08, a09, 0x5410u), ar2 = prmt(a08, a09, 0x7632u);
        unsigned ap3 = prmt(a18, a19, 0x5410u), ar3 = prmt(a18, a19, 0x7632u);
#pragma unroll
        for (int nt = 0; nt < 16; nt++) {
            int n = nt*8 + g;
            unsigned w00 = sW[ c0     *FS + n], w01 = sW[(c0 + 1)*FS + n];
            unsigned w08 = sW[(c0 + 8)*FS + n], w09 = sW[(c0 + 9)*FS + n];
            unsigned bp0 = prmt(w00, w01, 0x5410u), br0 = prmt(w00, w01, 0x7632u);
            unsigned bp1 = prmt(w08, w09, 0x5410u), br1 = prmt(w08, w09, 0x7632u);
            mma16(d[nt], ap0, ap1, ap2, ap3, bp0, bp1);
            mma16(d[nt], ap0, ap1, ap2, ap3, br0, br1);
            mma16(d[nt], ar0, ar1, ar2, ar3, bp0, bp1);
        }
    }

    float pA = 0.f, pB = 0.f;
#pragma unroll
    for (int nt = 0; nt < 16; nt++) {
        int d0 = nt*8 + 2*t4, d1 = d0 + 1;
        float bb0 = sb1[d0], bb1 = sb1[d1];
        float ww0 = sw2[d0], ww1 = sw2[d1];
        float u;
        u = d[nt][0] + bb0; u = 0.5f*u*(1.f + erff(u*0.70710678118654752f)); pA += u*ww0;
        u = d[nt][1] + bb1; u = 0.5f*u*(1.f + erff(u*0.70710678118654752f)); pA += u*ww1;
        u = d[nt][2] + bb0; u = 0.5f*u*(1.f + erff(u*0.70710678118654752f)); pB += u*ww0;
        u = d[nt][3] + bb1; u = 0.5f*u*(1.f + erff(u*0.70710678118654752f)); pB += u*ww1;
    }
    pA += __shfl_xor_sync(0xffffffffu, pA, 1);
    pA += __shfl_xor_sync(0xffffffffu, pA, 2);
    pB += __shfl_xor_sync(0xffffffffu, pB, 1);
    pB += __shfl_xor_sync(0xffffffffu, pB, 2);
    if (t4 == 0) {
        float bias2 = b2[0];
        size_t base = ((size_t)b*256 + y)*256 + x0 + wid*16 + g;
        out[base    ] = pA + bias2;
        out[base + 8] = pB + bias2;
    }
}

// ---------------- launcher ----------------
extern "C" void kernel_launch(void* const* d_in, const int* in_sizes, int n_in,
                              void* d_out, int out_size) {
    const float* x     = (const float*)d_in[0];
    const float* fc0_w = (const float*)d_in[1];
    const float* fc0_b = (const float*)d_in[2];
    const float* sc_w  = (const float*)d_in[3];
    const float* pw_w  = (const float*)d_in[4];
    const float* pw_b  = (const float*)d_in[5];
    const float* fc1_w = (const float*)d_in[6];
    const float* fc1_b = (const float*)d_in[7];
    const float* fc2_w = (const float*)d_in[8];
    const float* fc2_b = (const float*)d_in[9];
    float* out = (float*)d_out;

    k_E<<<1, 256>>>();
    k_tw<<<1, 256>>>();
    k_lift<<<65536, 256>>>(x, fc0_w, fc0_b);
    k_fwd<<<1024, 256>>>(0);
    k_wt<<<18432, 256>>>(sc_w);
    k_pws<<<64, 256>>>(pw_w);
    k_w1p<<<32, 256>>>(fc1_w);
    k_mix<<<1152, 256>>>(0);
    k_inv_h<<<1024, 256>>>();
    k_combine<<<4096, 256>>>(pw_b, 0);
    for (int l = 1; l < 4; l++) {
        k_fwd<<<1024, 256>>>(l);
        k_mix<<<1152, 256>>>(l);
        k_inv_h<<<1024, 256>>>();
        k_combine<<<4096, 256>>>(pw_b, l);
    }
    k_final<<<8192, 256>>>(fc1_b, fc2_w, fc2_b, out);
}

// round 13
// speedup vs baseline: 1.3027x; 1.0339x over previous
#include <cuda_runtime.h>
#include <cuda_bf16.h>
#include <math.h>

#define BB 16
#define HH 256
#define WW 256
#define CC 64
#define M2K 12
#define NKY 24
#define FCH 128

// ---------------- device-global scratch ----------------
__device__ float    g_hA [(size_t)BB*CC*HH*WW];   // fp32 h (final layer only)
__device__ unsigned g_hPA[(size_t)BB*CC*HH*WW];   // split-packed h ping
__device__ unsigned g_hPB[(size_t)BB*CC*HH*WW];   // split-packed h pong
__device__ float2 g_xf[(size_t)BB*CC*NKY*M2K];
__device__ float2 g_yf[(size_t)BB*CC*NKY*M2K];
__device__ float2 g_g [(size_t)BB*CC*HH*M2K];
__device__ float2 g_wt[(size_t)4*NKY*M2K*CC*CC];
__device__ float2 g_tw[256];
__device__ unsigned g_EP2[24*128];   // fwd E, x-pair primary plane [n][x2]
__device__ unsigned g_ER2[24*128];   // fwd E, x-pair residual plane
__device__ unsigned g_EIpP[12*256];  // inverse-W (alpha-scaled), e-pair primary [e2][x]
__device__ unsigned g_EIpR[12*256];  // residual plane
__device__ unsigned g_pwpP[4*CC*32]; // pointwise weights, k-pair primary [l][o][i2]
__device__ unsigned g_pwpR[4*CC*32];
__device__ unsigned g_w1pP[32*FCH];  // fc1 weights, c-pair primary [c2][d]
__device__ unsigned g_w1pR[32*FCH];

// ---------------- bf16 split-pack helpers ----------------
__device__ __forceinline__ unsigned split2(float a) {
    __nv_bfloat16 p = __float2bfloat16_rn(a);
    float pf = __bfloat162float(p);
    __nv_bfloat16 r = __float2bfloat16_rn(a - pf);
    return ((unsigned)__bfloat16_as_ushort(r) << 16) | (unsigned)__bfloat16_as_ushort(p);
}
__device__ __forceinline__ unsigned prmt(unsigned a, unsigned b, unsigned s) {
    unsigned d;
    asm("prmt.b32 %0, %1, %2, %3;" : "=r"(d) : "r"(a), "r"(b), "r"(s));
    return d;
}
__device__ __forceinline__ void mma_bf16(float d[4], unsigned a0, unsigned a1, unsigned b0) {
    asm volatile("mma.sync.aligned.m16n8k8.row.col.f32.bf16.bf16.f32 "
        "{%0,%1,%2,%3}, {%4,%5}, {%6}, {%0,%1,%2,%3};"
        : "+f"(d[0]), "+f"(d[1]), "+f"(d[2]), "+f"(d[3])
        : "r"(a0), "r"(a1), "r"(b0));
}
__device__ __forceinline__ void mma16(float d[4], unsigned a0, unsigned a1,
                                      unsigned a2, unsigned a3,
                                      unsigned b0, unsigned b1) {
    asm volatile("mma.sync.aligned.m16n8k16.row.col.f32.bf16.bf16.f32 "
        "{%0,%1,%2,%3}, {%4,%5,%6,%7}, {%8,%9}, {%0,%1,%2,%3};"
        : "+f"(d[0]), "+f"(d[1]), "+f"(d[2]), "+f"(d[3])
        : "r"(a0), "r"(a1), "r"(a2), "r"(a3), "r"(b0), "r"(b1));
}
__device__ __forceinline__ void cp_async16(unsigned smem_addr, const void* gptr) {
    asm volatile("cp.async.cg.shared.global [%0], [%1], 16;"
                 :: "r"(smem_addr), "l"(gptr));
}

// ---------------- table builders ----------------
__global__ void k_tw() {
    int m = threadIdx.x;
    double s, c;
    sincospi((double)m / 128.0, &s, &c);
    g_tw[m]  = make_float2((float)c, (float)s);
}

__global__ void k_E() {
    int tid = threadIdx.x;
    // fwd E pairs along x: E[x][2j]=cos(jx), E[x][2j+1]=-sin(jx)
    if (tid < 128) {
        int x2 = tid;
#pragma unroll
        for (int j = 0; j < 12; j++) {
            double s0, c0, s1, c1;
            sincospi((double)((j * (2*x2    )) & 255) / 128.0, &s0, &c0);
            sincospi((double)((j * (2*x2 + 1)) & 255) / 128.0, &s1, &c1);
            unsigned pc0 = split2((float)c0), pc1 = split2((float)c1);
            unsigned ps0 = split2(-(float)s0), ps1 = split2(-(float)s1);
            g_EP2[(2*j    )*128 + x2] = prmt(pc0, pc1, 0x5410u);
            g_ER2[(2*j    )*128 + x2] = prmt(pc0, pc1, 0x7632u);
            g_EP2[(2*j + 1)*128 + x2] = prmt(ps0, ps1, 0x5410u);
            g_ER2[(2*j + 1)*128 + x2] = prmt(ps0, ps1, 0x7632u);
        }
    }
    // inverse EI pairs along e: EI[e][x] = alpha_e cos(ex) (e<12) | -A2 sin((e-12)x)
    {
        int x = tid;
        const float A1 = 1.f/65536.f, A2 = 2.f/65536.f;
#pragma unroll
        for (int e2 = 0; e2 < 12; e2++) {
            float v[2];
#pragma unroll
            for (int h = 0; h < 2; h++) {
                int e = 2*e2 + h;
                double s, c;
                if (e < 12) {
                    sincospi((double)((e * x) & 255) / 128.0, &s, &c);
                    v[h] = ((e == 0) ? A1 : A2) * (float)c;
                } else {
                    int j = e - 12;
                    sincospi((double)((j * x) & 255) / 128.0, &s, &c);
                    v[h] = -A2 * (float)s;
                }
            }
            unsigned p0 = split2(v[0]), p1 = split2(v[1]);
            g_EIpP[e2*256 + x] = prmt(p0, p1, 0x5410u);
            g_EIpR[e2*256 + x] = prmt(p0, p1, 0x7632u);
        }
    }
}

// pointwise weights: pair along i
__global__ void k_pws(const float* __restrict__ pw) {
    int idx = blockIdx.x * 256 + threadIdx.x;   // 8192 = 4*64*32
    int i2 = idx & 31;
    int base = (idx >> 5) * 64;                 // (l*64+o)*64
    unsigned s0 = split2(pw[base + 2*i2]);
    unsigned s1 = split2(pw[base + 2*i2 + 1]);
    g_pwpP[idx] = prmt(s0, s1, 0x5410u);
    g_pwpR[idx] = prmt(s0, s1, 0x7632u);
}
// fc1 weights: pair along c
__global__ void k_w1p(const float* __restrict__ w1) {
    int idx = blockIdx.x * 256 + threadIdx.x;   // 4096 = 32*128
    int c2 = idx >> 7, d = idx & 127;
    unsigned s0 = split2(w1[(2*c2    )*128 + d]);
    unsigned s1 = split2(w1[(2*c2 + 1)*128 + d]);
    g_w1pP[idx] = prmt(s0, s1, 0x5410u);
    g_w1pR[idx] = prmt(s0, s1, 0x7632u);
}

// ---------------- spectral weight transpose ----------------
__global__ void k_wt(const float* __restrict__ scw) {
    size_t idx = (size_t)blockIdx.x * 256 + threadIdx.x;
    if (idx >= (size_t)4*2*CC*CC*144) return;
    size_t t = idx;
    int kx = t % 12; t /= 12;
    int ky = t % 12; t /= 12;
    int o  = t % CC; t /= CC;
    int i  = t % CC; t /= CC;
    int p  = t % 2;  t /= 2;
    int l  = (int)t;
    float re = scw[idx*2], im = scw[idx*2+1];
    int kyi = (p == 0) ? ky : (12 + ky);
    size_t dst = ((((size_t)l*NKY + kyi)*12 + kx)*CC + i)*CC + o;
    g_wt[dst] = make_float2(re, im);
}

// ---------------- lift: writes split-packed h ----------------
__global__ void k_lift(const float* __restrict__ x, const float* __restrict__ w,
                       const float* __restrict__ b) {
    size_t i4 = (size_t)blockIdx.x * 256 + threadIdx.x;
    int x4 = i4 & 63;
    int y  = (i4 >> 6) & 255;
    int c  = (i4 >> 14) & 63;
    int bb = (int)(i4 >> 20);
    float4 xv = ((const float4*)x)[((size_t)bb*256 + y)*64 + x4];
    float wc = w[c], bc = b[c];
    uint4 o;
    o.x = split2(xv.x*wc + bc); o.y = split2(xv.y*wc + bc);
    o.z = split2(xv.z*wc + bc); o.w = split2(xv.w*wc + bc);
    ((uint4*)g_hPA)[i4] = o;
}

// ---------------- fused forward: W-DFT GEMM + H-DFT ----------------
// pool layout (words): sEp[0,3168) sEr[3168,6336) buf0@6336(5120) buf1@11456(5120)
#define ESTT 132
#define BST 20
#define OFF_B0 6336
#define OFF_B1 11456
__global__ void __launch_bounds__(256, 3) k_fwd(int l) {
    const unsigned* hin = (l & 1) ? g_hPB : g_hPA;
    __shared__ __align__(16) unsigned s_pool[16576];
    unsigned* sEp = s_pool;
    unsigned* sEr = s_pool + 3168;
    int tid = threadIdx.x;
    int bc = blockIdx.x;
    const unsigned* hbase = hin + ((size_t)bc << 16);

    for (int t = tid; t < 768; t += 256) {   // 24 rows x 32 uint4
        int n = t >> 5, q = t & 31;
        *(uint4*)&sEp[n*ESTT + q*4] = ((const uint4*)g_EP2)[n*32 + q];
        *(uint4*)&sEr[n*ESTT + q*4] = ((const uint4*)g_ER2)[n*32 + q];
    }

    {
        unsigned* sB = s_pool + OFF_B0;
#pragma unroll
        for (int it = 0; it < 4; it++) {
            int idx = it*256 + tid;
            int r = idx >> 2, q = idx & 3;
            cp_async16((unsigned)__cvta_generic_to_shared(&sB[r*BST + q*4]),
                       hbase + (r << 8) + q*4);
        }
        asm volatile("cp.async.commit_group;");
    }

    int wid = tid >> 5, lane = tid & 31, g = lane >> 2, t4 = lane & 3;
    float d[2][3][4];
#pragma unroll
    for (int mt = 0; mt < 2; mt++)
#pragma unroll
        for (int nt = 0; nt < 3; nt++)
#pragma unroll
            for (int r = 0; r < 4; r++) d[mt][nt][r] = 0.f;

#pragma unroll 1
    for (int xc = 0; xc < 16; xc++) {
        unsigned* sB = s_pool + ((xc & 1) ? OFF_B1 : OFF_B0);
        if (xc < 15) {
            unsigned* sN = s_pool + ((xc & 1) ? OFF_B0 : OFF_B1);
            int xn = (xc + 1) * 16;
#pragma unroll
            for (int it = 0; it < 4; it++) {
                int idx = it*256 + tid;
                int r = idx >> 2, q = idx & 3;
                cp_async16((unsigned)__cvta_generic_to_shared(&sN[r*BST + q*4]),
                           hbase + (r << 8) + xn + q*4);
            }
            asm volatile("cp.async.commit_group;");
            asm volatile("cp.async.wait_group 1;");
        } else {
            asm volatile("cp.async.wait_group 0;");
        }
        __syncthreads();

        {
            int ko = 2*t4;
            int xp0 = xc*8 + t4;             // x-pair index
            unsigned ap[2][4], ar[2][4];
#pragma unroll
            for (int mt = 0; mt < 2; mt++) {
                int r0 = wid*32 + mt*16 + g;
                uint2 L00 = *(const uint2*)&sB[ r0     *BST + ko];
                uint2 L08 = *(const uint2*)&sB[ r0     *BST + ko + 8];
                uint2 L10 = *(const uint2*)&sB[(r0 + 8)*BST + ko];
                uint2 L18 = *(const uint2*)&sB[(r0 + 8)*BST + ko + 8];
                ap[mt][0] = prmt(L00.x, L00.y, 0x5410u); ar[mt][0] = prmt(L00.x, L00.y, 0x7632u);
                ap[mt][1] = prmt(L10.x, L10.y, 0x5410u); ar[mt][1] = prmt(L10.x, L10.y, 0x7632u);
                ap[mt][2] = prmt(L08.x, L08.y, 0x5410u); ar[mt][2] = prmt(L08.x, L08.y, 0x7632u);
                ap[mt][3] = prmt(L18.x, L18.y, 0x5410u); ar[mt][3] = prmt(L18.x, L18.y, 0x7632u);
            }
#pragma unroll
            for (int nt = 0; nt < 3; nt++) {
                int n = nt*8 + g;
                unsigned bp0 = sEp[n*ESTT + xp0];
                unsigned bp1 = sEp[n*ESTT + xp0 + 4];
                unsigned br0 = sEr[n*ESTT + xp0];
                unsigned br1 = sEr[n*ESTT + xp0 + 4];
#pragma unroll
                for (int mt = 0; mt < 2; mt++) {
                    mma16(d[mt][nt], ap[mt][0], ap[mt][1], ap[mt][2], ap[mt][3], bp0, bp1);
                    mma16(d[mt][nt], ap[mt][0], ap[mt][1], ap[mt][2], ap[mt][3], br0, br1);
                    mma16(d[mt][nt], ar[mt][0], ar[mt][1], ar[mt][2], ar[mt][3], bp0, bp1);
                }
            }
        }
        __syncthreads();
    }

    // phase 2: Xw -> smem, H-DFT, write g_xf
    float2* sXw = (float2*)(s_pool + OFF_B0);    // [y][kx] stride 13 -> 6656 words
    float2* stw = (float2*)(s_pool + 12992);
#pragma unroll
    for (int mt = 0; mt < 2; mt++) {
        int r0 = wid*32 + mt*16 + g;
#pragma unroll
        for (int nt = 0; nt < 3; nt++) {
            int kx = nt*4 + t4;
            sXw[ r0     *13 + kx] = make_float2(d[mt][nt][0], d[mt][nt][1]);
            sXw[(r0 + 8)*13 + kx] = make_float2(d[mt][nt][2], d[mt][nt][3]);
        }
    }
    stw[tid] = g_tw[tid];
    __syncthreads();

    for (int cell = tid; cell < 288; cell += 256) {
        int kyi = cell / 12, kx = cell % 12;
        int ky  = (kyi < 12) ? kyi : (kyi + 232);
        float ar2 = 0.f, ai2 = 0.f;
        for (int y = 0; y < 256; y++) {
            float2 a = sXw[y*13 + kx];
            float2 w = stw[(ky*y) & 255];
            ar2 += a.x*w.x + a.y*w.y;
            ai2 += a.y*w.x - a.x*w.y;
        }
        g_xf[(size_t)bc*288 + cell] = make_float2(ar2, ai2);
    }
}

// ---------------- mode mixing ----------------
__global__ void k_mix(int l) {
    __shared__ float2 sxf[4][64];
    int b = blockIdx.x / 72, grp = blockIdx.x % 72;
    int cell0 = grp * 4;
    {
        int c = threadIdx.x >> 6, i = threadIdx.x & 63;
        sxf[c][i] = g_xf[((size_t)b*CC + i)*288 + cell0 + c];
    }
    __syncthreads();
    int cc = threadIdx.x >> 6, o = threadIdx.x & 63;
    int cell = cell0 + cc;
    int kyi = cell / 12, kx = cell % 12;
    const float2* wp = g_wt + (((size_t)l*NKY + kyi)*12 + kx)*4096 + o;
    float ar = 0.f, ai = 0.f;
#pragma unroll 8
    for (int i = 0; i < 64; i++) {
        float2 a = sxf[cc][i];
        float2 w = wp[(size_t)i * 64];
        ar += a.x*w.x - a.y*w.y;
        ai += a.x*w.y + a.y*w.x;
    }
    g_yf[((size_t)b*CC + o)*288 + cell] = make_float2(ar, ai);
}

// ---------------- inverse H ----------------
__global__ void k_inv_h() {
    __shared__ float2 sy[288];
    __shared__ float2 tw[256];
    int bo = blockIdx.x;
    for (int t = threadIdx.x; t < 256; t += 256) tw[t] = g_tw[t];
    for (int t = threadIdx.x; t < 288; t += 256) sy[t] = g_yf[(size_t)bo*288 + t];
    __syncthreads();
    int y = threadIdx.x;
    float2 acc[12];
#pragma unroll
    for (int kx = 0; kx < 12; kx++) acc[kx] = make_float2(0.f, 0.f);
    for (int kyi = 0; kyi < 24; kyi++) {
        int ky = (kyi < 12) ? kyi : (kyi + 232);
        float2 w = tw[(ky*y) & 255];
#pragma unroll
        for (int kx = 0; kx < 12; kx++) {
            float2 a = sy[kyi*12 + kx];
            acc[kx].x += a.x*w.x - a.y*w.y;
            acc[kx].y += a.x*w.y + a.y*w.x;
        }
    }
#pragma unroll
    for (int kx = 0; kx < 12; kx++)
        g_g[((size_t)bo*256 + y)*12 + kx] = acc[kx];
}

// ---------------- fused combine: pre-paired planes, uniform K=88 ----------------
#define APR 44
#define BPR 72
#define XP 68
__global__ void __launch_bounds__(256) k_combine(const float* __restrict__ pw_b, int l) {
    const unsigned* hin = (l & 1) ? g_hPB : g_hPA;
    unsigned* hpout = (l & 1) ? g_hPA : g_hPB;
    __shared__ __align__(16) unsigned sAp[64*APR];   // [o][kpair]
    __shared__ __align__(16) unsigned sAr[64*APR];
    __shared__ __align__(16) unsigned sBp[44*BPR];   // [kpair][x] (pairs 0-31 h, 32-43 EI)
    __shared__ __align__(16) unsigned sBr[44*BPR];
    __shared__ __align__(16) float    sD[64*XP];
    __shared__ float  sbias[64];

    int y = blockIdx.x & 255;
    int b = blockIdx.x >> 8;
    int tid = threadIdx.x;

    // sA: pre-paired weights (direct copy)
#pragma unroll
    for (int it = 0; it < 2; it++) {
        int t = it*256 + tid;            // 512 uint4 slots
        int o = t >> 3, q = t & 7;
        *(uint4*)&sAp[o*APR + q*4] = *(const uint4*)(g_pwpP + (l*64 + o)*32 + q*4);
        *(uint4*)&sAr[o*APR + q*4] = *(const uint4*)(g_pwpR + (l*64 + o)*32 + q*4);
    }
    // sA: spectral G pairs (Gr at 32+j2, Gi at 38+j2)
#pragma unroll
    for (int it = 0; it < 2; it++) {
        int t = it*256 + tid;
        if (t < 384) {
            int o = t / 6, j2 = t % 6;
            float4 gq = *(const float4*)(g_g + (((size_t)b*64 + o)*256 + y)*12 + 2*j2);
            unsigned sr0 = split2(gq.x), si0 = split2(gq.y);
            unsigned sr1 = split2(gq.z), si1 = split2(gq.w);
            sAp[o*APR + 32 + j2] = prmt(sr0, sr1, 0x5410u);
            sAr[o*APR + 32 + j2] = prmt(sr0, sr1, 0x7632u);
            sAp[o*APR + 38 + j2] = prmt(si0, si1, 0x5410u);
            sAr[o*APR + 38 + j2] = prmt(si0, si1, 0x7632u);
        }
    }
    if (tid < 64) sbias[tid] = pw_b[l*64 + tid];

    int wid = tid >> 5, lane = tid & 31;
    int mt = wid & 3, nh = wid >> 2;
    int g = lane >> 2, t4 = lane & 3;

    // prefetch chunk 0 h rows (pair rows 2p, 2p+1)
    uint4 pf[4];
#pragma unroll
    for (int it = 0; it < 2; it++) {
        int s = it*256 + tid;            // 512 pair-slots
        int p = s >> 4, q = s & 15;
        size_t rb = (((size_t)b*64 + 2*p)*256 + y) << 8;
        pf[2*it    ] = *(const uint4*)(hin + rb + q*4);
        pf[2*it + 1] = *(const uint4*)(hin + rb + 65536 + q*4);
    }

#pragma unroll 1
    for (int xc = 0; xc < 4; xc++) {
        int x0 = xc << 6;
        // commit h pairs
#pragma unroll
        for (int it = 0; it < 2; it++) {
            int s = it*256 + tid;
            int p = s >> 4, q = s & 15;
            uint4 u = pf[2*it], v = pf[2*it + 1];
            uint4 P, R;
            P.x = prmt(u.x, v.x, 0x5410u); R.x = prmt(u.x, v.x, 0x7632u);
            P.y = prmt(u.y, v.y, 0x5410u); R.y = prmt(u.y, v.y, 0x7632u);
            P.z = prmt(u.z, v.z, 0x5410u); R.z = prmt(u.z, v.z, 0x7632u);
            P.w = prmt(u.w, v.w, 0x5410u); R.w = prmt(u.w, v.w, 0x7632u);
            *(uint4*)&sBp[p*BPR + q*4] = P;
            *(uint4*)&sBr[p*BPR + q*4] = R;
        }
        // EI rows (pairs 32..43)
        if (tid < 192) {
            int e2 = tid >> 4, q = tid & 15;
            *(uint4*)&sBp[(32 + e2)*BPR + q*4] = *(const uint4*)(g_EIpP + e2*256 + x0 + q*4);
            *(uint4*)&sBr[(32 + e2)*BPR + q*4] = *(const uint4*)(g_EIpR + e2*256 + x0 + q*4);
        }
        __syncthreads();
        // prefetch next
        if (xc < 3) {
#pragma unroll
            for (int it = 0; it < 2; it++) {
                int s = it*256 + tid;
                int p = s >> 4, q = s & 15;
                size_t rb = (((size_t)b*64 + 2*p)*256 + y) << 8;
                pf[2*it    ] = *(const uint4*)(hin + rb + x0 + 64 + q*4);
                pf[2*it + 1] = *(const uint4*)(hin + rb + 65536 + x0 + 64 + q*4);
            }
        }

        float d[4][4];
#pragma unroll
        for (int nt = 0; nt < 4; nt++)
#pragma unroll
            for (int r = 0; r < 4; r++) d[nt][r] = 0.f;

        // 5 k16 tiles (pairs kt*8+t4, +4)
#pragma unroll
        for (int kt = 0; kt < 5; kt++) {
            int kp = kt*8 + t4;
            int ra = (mt*16 + g)*APR, rb2 = (mt*16 + g + 8)*APR;
            unsigned ap0 = sAp[ra  + kp], ap2 = sAp[ra  + kp + 4];
            unsigned ap1 = sAp[rb2 + kp], ap3 = sAp[rb2 + kp + 4];
            unsigned ar0 = sAr[ra  + kp], ar2 = sAr[ra  + kp + 4];
            unsigned ar1 = sAr[rb2 + kp], ar3 = sAr[rb2 + kp + 4];
#pragma unroll
            for (int nt = 0; nt < 4; nt++) {
                int xl = nh*32 + nt*8 + g;
                unsigned bp0 = sBp[ kp      *BPR + xl];
                unsigned bp1 = sBp[(kp + 4) *BPR + xl];
                unsigned br0 = sBr[ kp      *BPR + xl];
                unsigned br1 = sBr[(kp + 4) *BPR + xl];
                mma16(d[nt], ap0, ap1, ap2, ap3, bp0, bp1);
                mma16(d[nt], ap0, ap1, ap2, ap3, br0, br1);
                mma16(d[nt], ar0, ar1, ar2, ar3, bp0, bp1);
            }
        }
        // k8 tail (pairs 40+t4)
        {
            int kp = 40 + t4;
            unsigned ap0 = sAp[(mt*16 + g    )*APR + kp];
            unsigned ap1 = sAp[(mt*16 + g + 8)*APR + kp];
            unsigned ar0 = sAr[(mt*16 + g    )*APR + kp];
            unsigned ar1 = sAr[(mt*16 + g + 8)*APR + kp];
#pragma unroll
            for (int nt = 0; nt < 4; nt++) {
                int xl = nh*32 + nt*8 + g;
                unsigned bp = sBp[kp*BPR + xl];
                unsigned br = sBr[kp*BPR + xl];
                mma_bf16(d[nt], ap0, ap1, bp);
                mma_bf16(d[nt], ap0, ap1, br);
                mma_bf16(d[nt], ar0, ar1, bp);
            }
        }

#pragma unroll
        for (int nt = 0; nt < 4; nt++) {
            int xl = nh*32 + nt*8 + 2*t4;
            int o0 = mt*16 + g;
            *(float2*)&sD[ o0      * XP + xl] = make_float2(d[nt][0], d[nt][1]);
            *(float2*)&sD[(o0 + 8) * XP + xl] = make_float2(d[nt][2], d[nt][3]);
        }
        __syncthreads();

#pragma unroll
        for (int it = 0; it < 4; it++) {
            int o  = it*16 + (tid >> 4);
            int x4 = tid & 15;
            float4 v = *(float4*)&sD[o*XP + x4*4];
            float bias = sbias[o];
            size_t base = ((((size_t)b*64 + o)*256 + y) << 8) + x0 + x4*4;
            if (l < 3) {
                float u0 = v.x + bias, u1 = v.y + bias, u2 = v.z + bias, u3 = v.w + bias;
                u0 = 0.5f*u0*(1.f + erff(u0*0.70710678118654752f));
                u1 = 0.5f*u1*(1.f + erff(u1*0.70710678118654752f));
                u2 = 0.5f*u2*(1.f + erff(u2*0.70710678118654752f));
                u3 = 0.5f*u3*(1.f + erff(u3*0.70710678118654752f));
                uint4 up;
                up.x = split2(u0); up.y = split2(u1); up.z = split2(u2); up.w = split2(u3);
                *(uint4*)(hpout + base) = up;
            } else {
                v.x += bias; v.y += bias; v.z += bias; v.w += bias;
                *(float4*)(g_hA + base) = v;
            }
        }
        __syncthreads();
    }
}

// ---------------- final: pre-paired fc1 (k16) + gelu + fc2 ----------------
#define FSP 136
__global__ void __launch_bounds__(256) k_final(const float* __restrict__ b1,
                        const float* __restrict__ w2, const float* __restrict__ b2,
                        float* __restrict__ out) {
    __shared__ __align__(16) unsigned sHp[32*FSP];   // [c2][x]
    __shared__ __align__(16) unsigned sHr[32*FSP];
    __shared__ __align__(16) unsigned sWp[32*FSP];   // [c2][d]
    __shared__ __align__(16) unsigned sWr[32*FSP];
    __shared__ float sb1[FCH];
    __shared__ float sw2[FCH];
    int xh = blockIdx.x & 1;
    int y  = (blockIdx.x >> 1) & 255;
    int b  = blockIdx.x >> 9;
    int tid = threadIdx.x;
    int x0 = xh << 7;

    // h pairs along c
#pragma unroll
    for (int it = 0; it < 4; it++) {
        int s = it*256 + tid;            // 1024 = 32 pairs x 32 uint4
        int c2 = s >> 5, q = s & 31;
        size_t rb = (((size_t)b*64 + 2*c2)*256 + y) << 8;
        float4 ua = *(const float4*)(g_hA + rb + x0 + q*4);
        float4 ub = *(const float4*)(g_hA + rb + 65536 + x0 + q*4);
        unsigned a0 = split2(ua.x), b0 = split2(ub.x);
        unsigned a1 = split2(ua.y), b1 = split2(ub.y);
        unsigned a2 = split2(ua.z), b2s = split2(ub.z);
        unsigned a3 = split2(ua.w), b3 = split2(ub.w);
        uint4 P, R;
        P.x = prmt(a0, b0, 0x5410u); R.x = prmt(a0, b0, 0x7632u);
        P.y = prmt(a1, b1, 0x5410u); R.y = prmt(a1, b1, 0x7632u);
        P.z = prmt(a2, b2s, 0x5410u); R.z = prmt(a2, b2s, 0x7632u);
        P.w = prmt(a3, b3, 0x5410u); R.w = prmt(a3, b3, 0x7632u);
        *(uint4*)&sHp[c2*FSP + q*4] = P;
        *(uint4*)&sHr[c2*FSP + q*4] = R;
    }
    // fc1 weight pairs (direct copy)
#pragma unroll
    for (int it = 0; it < 4; it++) {
        int s = it*256 + tid;
        int c2 = s >> 5, q = s & 31;
        *(uint4*)&sWp[c2*FSP + q*4] = ((const uint4*)g_w1pP)[c2*32 + q];
        *(uint4*)&sWr[c2*FSP + q*4] = ((const uint4*)g_w1pR)[c2*32 + q];
    }
    if (tid < 128) { sb1[tid] = b1[tid]; sw2[tid] = w2[tid]; }
    __syncthreads();

    int wid = tid >> 5, lane = tid & 31;
    int g = lane >> 2, t4 = lane & 3;
    float d[16][4];
#pragma unroll
    for (int nt = 0; nt < 16; nt++)
#pragma unroll
        for (int r = 0; r < 4; r++) d[nt][r] = 0.f;

#pragma unroll
    for (int kt = 0; kt < 4; kt++) {
        int kp = kt*8 + t4;
        int X0 = wid*16 + g;
        unsigned ap0 = sHp[ kp     *FSP + X0], ap1 = sHp[ kp     *FSP + X0 + 8];
        unsigned ap2 = sHp[(kp + 4)*FSP + X0], ap3 = sHp[(kp + 4)*FSP + X0 + 8];
        unsigned ar0 = sHr[ kp     *FSP + X0], ar1 = sHr[ kp     *FSP + X0 + 8];
        unsigned ar2 = sHr[(kp + 4)*FSP + X0], ar3 = sHr[(kp + 4)*FSP + X0 + 8];
#pragma unroll
        for (int nt = 0; nt < 16; nt++) {
            int n = nt*8 + g;
            unsigned bp0 = sWp[ kp     *FSP + n];
            unsigned bp1 = sWp[(kp + 4)*FSP + n];
            unsigned br0 = sWr[ kp     *FSP + n];
            unsigned br1 = sWr[(kp + 4)*FSP + n];
            mma16(d[nt], ap0, ap1, ap2, ap3, bp0, bp1);
            mma16(d[nt], ap0, ap1, ap2, ap3, br0, br1);
            mma16(d[nt], ar0, ar1, ar2, ar3, bp0, bp1);
        }
    }

    float pA = 0.f, pB = 0.f;
#pragma unroll
    for (int nt = 0; nt < 16; nt++) {
        int d0 = nt*8 + 2*t4, d1 = d0 + 1;
        float bb0 = sb1[d0], bb1 = sb1[d1];
        float ww0 = sw2[d0], ww1 = sw2[d1];
        float u;
        u = d[nt][0] + bb0; u = 0.5f*u*(1.f + erff(u*0.70710678118654752f)); pA += u*ww0;
        u = d[nt][1] + bb1; u = 0.5f*u*(1.f + erff(u*0.70710678118654752f)); pA += u*ww1;
        u = d[nt][2] + bb0; u = 0.5f*u*(1.f + erff(u*0.70710678118654752f)); pB += u*ww0;
        u = d[nt][3] + bb1; u = 0.5f*u*(1.f + erff(u*0.70710678118654752f)); pB += u*ww1;
    }
    pA += __shfl_xor_sync(0xffffffffu, pA, 1);
    pA += __shfl_xor_sync(0xffffffffu, pA, 2);
    pB += __shfl_xor_sync(0xffffffffu, pB, 1);
    pB += __shfl_xor_sync(0xffffffffu, pB, 2);
    if (t4 == 0) {
        float bias2 = b2[0];
        size_t base = ((size_t)b*256 + y)*256 + x0 + wid*16 + g;
        out[base    ] = pA + bias2;
        out[base + 8] = pB + bias2;
    }
}

// ---------------- launcher ----------------
extern "C" void kernel_launch(void* const* d_in, const int* in_sizes, int n_in,
                              void* d_out, int out_size) {
    const float* x     = (const float*)d_in[0];
    const float* fc0_w = (const float*)d_in[1];
    const float* fc0_b = (const float*)d_in[2];
    const float* sc_w  = (const float*)d_in[3];
    const float* pw_w  = (const float*)d_in[4];
    const float* pw_b  = (const float*)d_in[5];
    const float* fc1_w = (const float*)d_in[6];
    const float* fc1_b = (const float*)d_in[7];
    const float* fc2_w = (const float*)d_in[8];
    const float* fc2_b = (const float*)d_in[9];
    float* out = (float*)d_out;

    k_E<<<1, 256>>>();
    k_tw<<<1, 256>>>();
    k_lift<<<65536, 256>>>(x, fc0_w, fc0_b);
    k_fwd<<<1024, 256>>>(0);
    k_wt<<<18432, 256>>>(sc_w);
    k_pws<<<32, 256>>>(pw_w);
    k_w1p<<<16, 256>>>(fc1_w);
    k_mix<<<1152, 256>>>(0);
    k_inv_h<<<1024, 256>>>();
    k_combine<<<4096, 256>>>(pw_b, 0);
    for (int l = 1; l < 4; l++) {
        k_fwd<<<1024, 256>>>(l);
        k_mix<<<1152, 256>>>(l);
        k_inv_h<<<1024, 256>>>();
        k_combine<<<4096, 256>>>(pw_b, l);
    }
    k_final<<<8192, 256>>>(fc1_b, fc2_w, fc2_b, out);
}

// round 14
// speedup vs baseline: 1.3799x; 1.0593x over previous
#include <cuda_runtime.h>
#include <cuda_bf16.h>
#include <math.h>

#define BB 16
#define HH 256
#define WW 256
#define CC 64
#define M2K 12
#define NKY 24
#define FCH 128

// ---------------- device-global scratch ----------------
__device__ unsigned g_hPA[(size_t)BB*CC*HH*WW];   // split-packed h ping
__device__ unsigned g_hPB[(size_t)BB*CC*HH*WW];   // split-packed h pong
__device__ float2 g_xf[(size_t)BB*CC*NKY*M2K];
__device__ float2 g_yf[(size_t)BB*CC*NKY*M2K];
__device__ float2 g_g [(size_t)BB*CC*HH*M2K];
__device__ float2 g_wt[(size_t)4*NKY*M2K*CC*CC];
__device__ float2 g_tw[256];
__device__ unsigned g_EP2[24*128];   // fwd E, x-pair primary plane [n][x2]
__device__ unsigned g_ER2[24*128];   // fwd E, x-pair residual plane
__device__ unsigned g_EIpP[12*256];  // inverse-W (alpha-scaled), e-pair primary [e2][x]
__device__ unsigned g_EIpR[12*256];  // residual plane
__device__ unsigned g_pwpP[4*CC*32]; // pointwise weights, k-pair primary [l][o][i2]
__device__ unsigned g_pwpR[4*CC*32];
__device__ unsigned g_w1pP[32*FCH];  // fc1 weights, c-pair primary [c2][d]
__device__ unsigned g_w1pR[32*FCH];

// ---------------- bf16 split-pack helpers ----------------
__device__ __forceinline__ unsigned split2(float a) {
    __nv_bfloat16 p = __float2bfloat16_rn(a);
    float pf = __bfloat162float(p);
    __nv_bfloat16 r = __float2bfloat16_rn(a - pf);
    return ((unsigned)__bfloat16_as_ushort(r) << 16) | (unsigned)__bfloat16_as_ushort(p);
}
__device__ __forceinline__ unsigned prmt(unsigned a, unsigned b, unsigned s) {
    unsigned d;
    asm("prmt.b32 %0, %1, %2, %3;" : "=r"(d) : "r"(a), "r"(b), "r"(s));
    return d;
}
__device__ __forceinline__ void mma_bf16(float d[4], unsigned a0, unsigned a1, unsigned b0) {
    asm volatile("mma.sync.aligned.m16n8k8.row.col.f32.bf16.bf16.f32 "
        "{%0,%1,%2,%3}, {%4,%5}, {%6}, {%0,%1,%2,%3};"
        : "+f"(d[0]), "+f"(d[1]), "+f"(d[2]), "+f"(d[3])
        : "r"(a0), "r"(a1), "r"(b0));
}
__device__ __forceinline__ void mma16(float d[4], unsigned a0, unsigned a1,
                                      unsigned a2, unsigned a3,
                                      unsigned b0, unsigned b1) {
    asm volatile("mma.sync.aligned.m16n8k16.row.col.f32.bf16.bf16.f32 "
        "{%0,%1,%2,%3}, {%4,%5,%6,%7}, {%8,%9}, {%0,%1,%2,%3};"
        : "+f"(d[0]), "+f"(d[1]), "+f"(d[2]), "+f"(d[3])
        : "r"(a0), "r"(a1), "r"(a2), "r"(a3), "r"(b0), "r"(b1));
}
__device__ __forceinline__ void cp_async16(unsigned smem_addr, const void* gptr) {
    asm volatile("cp.async.cg.shared.global [%0], [%1], 16;"
                 :: "r"(smem_addr), "l"(gptr));
}
// exact-erf gelu via Abramowitz-Stegun 7.1.26 (|erf err| <= 1.5e-7 abs)
__device__ __forceinline__ float gelu_e(float v) {
    float x  = v * 0.70710678118654752f;
    float ax = fabsf(x);
    float t  = __fdividef(1.f, fmaf(0.3275911f, ax, 1.f));
    float p  = t*(0.254829592f + t*(-0.284496736f + t*(1.421413741f +
               t*(-1.453152027f + t*1.061405429f))));
    float e  = __expf(-x*x);
    float er = copysignf(1.f - p*e, x);
    return 0.5f * v * (1.f + er);
}

// ---------------- table builders ----------------
__global__ void k_tw() {
    int m = threadIdx.x;
    double s, c;
    sincospi((double)m / 128.0, &s, &c);
    g_tw[m]  = make_float2((float)c, (float)s);
}

__global__ void k_E() {
    int tid = threadIdx.x;
    if (tid < 128) {
        int x2 = tid;
#pragma unroll
        for (int j = 0; j < 12; j++) {
            double s0, c0, s1, c1;
            sincospi((double)((j * (2*x2    )) & 255) / 128.0, &s0, &c0);
            sincospi((double)((j * (2*x2 + 1)) & 255) / 128.0, &s1, &c1);
            unsigned pc0 = split2((float)c0), pc1 = split2((float)c1);
            unsigned ps0 = split2(-(float)s0), ps1 = split2(-(float)s1);
            g_EP2[(2*j    )*128 + x2] = prmt(pc0, pc1, 0x5410u);
            g_ER2[(2*j    )*128 + x2] = prmt(pc0, pc1, 0x7632u);
            g_EP2[(2*j + 1)*128 + x2] = prmt(ps0, ps1, 0x5410u);
            g_ER2[(2*j + 1)*128 + x2] = prmt(ps0, ps1, 0x7632u);
        }
    }
    {
        int x = tid;
        const float A1 = 1.f/65536.f, A2 = 2.f/65536.f;
#pragma unroll
        for (int e2 = 0; e2 < 12; e2++) {
            float v[2];
#pragma unroll
            for (int h = 0; h < 2; h++) {
                int e = 2*e2 + h;
                double s, c;
                if (e < 12) {
                    sincospi((double)((e * x) & 255) / 128.0, &s, &c);
                    v[h] = ((e == 0) ? A1 : A2) * (float)c;
                } else {
                    int j = e - 12;
                    sincospi((double)((j * x) & 255) / 128.0, &s, &c);
                    v[h] = -A2 * (float)s;
                }
            }
            unsigned p0 = split2(v[0]), p1 = split2(v[1]);
            g_EIpP[e2*256 + x] = prmt(p0, p1, 0x5410u);
            g_EIpR[e2*256 + x] = prmt(p0, p1, 0x7632u);
        }
    }
}

__global__ void k_pws(const float* __restrict__ pw) {
    int idx = blockIdx.x * 256 + threadIdx.x;
    int i2 = idx & 31;
    int base = (idx >> 5) * 64;
    unsigned s0 = split2(pw[base + 2*i2]);
    unsigned s1 = split2(pw[base + 2*i2 + 1]);
    g_pwpP[idx] = prmt(s0, s1, 0x5410u);
    g_pwpR[idx] = prmt(s0, s1, 0x7632u);
}
__global__ void k_w1p(const float* __restrict__ w1) {
    int idx = blockIdx.x * 256 + threadIdx.x;
    int c2 = idx >> 7, d = idx & 127;
    unsigned s0 = split2(w1[(2*c2    )*128 + d]);
    unsigned s1 = split2(w1[(2*c2 + 1)*128 + d]);
    g_w1pP[idx] = prmt(s0, s1, 0x5410u);
    g_w1pR[idx] = prmt(s0, s1, 0x7632u);
}

// ---------------- spectral weight transpose ----------------
__global__ void k_wt(const float* __restrict__ scw) {
    size_t idx = (size_t)blockIdx.x * 256 + threadIdx.x;
    if (idx >= (size_t)4*2*CC*CC*144) return;
    size_t t = idx;
    int kx = t % 12; t /= 12;
    int ky = t % 12; t /= 12;
    int o  = t % CC; t /= CC;
    int i  = t % CC; t /= CC;
    int p  = t % 2;  t /= 2;
    int l  = (int)t;
    float re = scw[idx*2], im = scw[idx*2+1];
    int kyi = (p == 0) ? ky : (12 + ky);
    size_t dst = ((((size_t)l*NKY + kyi)*12 + kx)*CC + i)*CC + o;
    g_wt[dst] = make_float2(re, im);
}

// ---------------- lift: writes split-packed h ----------------
__global__ void k_lift(const float* __restrict__ x, const float* __restrict__ w,
                       const float* __restrict__ b) {
    size_t i4 = (size_t)blockIdx.x * 256 + threadIdx.x;
    int x4 = i4 & 63;
    int y  = (i4 >> 6) & 255;
    int c  = (i4 >> 14) & 63;
    int bb = (int)(i4 >> 20);
    float4 xv = ((const float4*)x)[((size_t)bb*256 + y)*64 + x4];
    float wc = w[c], bc = b[c];
    uint4 o;
    o.x = split2(xv.x*wc + bc); o.y = split2(xv.y*wc + bc);
    o.z = split2(xv.z*wc + bc); o.w = split2(xv.w*wc + bc);
    ((uint4*)g_hPA)[i4] = o;
}

// ---------------- fused forward: W-DFT GEMM + H-DFT ----------------
#define ESTT 132
#define BST 20
#define OFF_B0 6336
#define OFF_B1 11456
__global__ void __launch_bounds__(256, 3) k_fwd(int l) {
    const unsigned* hin = (l & 1) ? g_hPB : g_hPA;
    __shared__ __align__(16) unsigned s_pool[16576];
    unsigned* sEp = s_pool;
    unsigned* sEr = s_pool + 3168;
    int tid = threadIdx.x;
    int bc = blockIdx.x;
    const unsigned* hbase = hin + ((size_t)bc << 16);

    for (int t = tid; t < 768; t += 256) {
        int n = t >> 5, q = t & 31;
        *(uint4*)&sEp[n*ESTT + q*4] = ((const uint4*)g_EP2)[n*32 + q];
        *(uint4*)&sEr[n*ESTT + q*4] = ((const uint4*)g_ER2)[n*32 + q];
    }

    {
        unsigned* sB = s_pool + OFF_B0;
#pragma unroll
        for (int it = 0; it < 4; it++) {
            int idx = it*256 + tid;
            int r = idx >> 2, q = idx & 3;
            cp_async16((unsigned)__cvta_generic_to_shared(&sB[r*BST + q*4]),
                       hbase + (r << 8) + q*4);
        }
        asm volatile("cp.async.commit_group;");
    }

    int wid = tid >> 5, lane = tid & 31, g = lane >> 2, t4 = lane & 3;
    float d[2][3][4];
#pragma unroll
    for (int mt = 0; mt < 2; mt++)
#pragma unroll
        for (int nt = 0; nt < 3; nt++)
#pragma unroll
            for (int r = 0; r < 4; r++) d[mt][nt][r] = 0.f;

#pragma unroll 1
    for (int xc = 0; xc < 16; xc++) {
        unsigned* sB = s_pool + ((xc & 1) ? OFF_B1 : OFF_B0);
        if (xc < 15) {
            unsigned* sN = s_pool + ((xc & 1) ? OFF_B0 : OFF_B1);
            int xn = (xc + 1) * 16;
#pragma unroll
            for (int it = 0; it < 4; it++) {
                int idx = it*256 + tid;
                int r = idx >> 2, q = idx & 3;
                cp_async16((unsigned)__cvta_generic_to_shared(&sN[r*BST + q*4]),
                           hbase + (r << 8) + xn + q*4);
            }
            asm volatile("cp.async.commit_group;");
            asm volatile("cp.async.wait_group 1;");
        } else {
            asm volatile("cp.async.wait_group 0;");
        }
        __syncthreads();

        {
            int ko = 2*t4;
            int xp0 = xc*8 + t4;
            unsigned ap[2][4], ar[2][4];
#pragma unroll
            for (int mt = 0; mt < 2; mt++) {
                int r0 = wid*32 + mt*16 + g;
                uint2 L00 = *(const uint2*)&sB[ r0     *BST + ko];
                uint2 L08 = *(const uint2*)&sB[ r0     *BST + ko + 8];
                uint2 L10 = *(const uint2*)&sB[(r0 + 8)*BST + ko];
                uint2 L18 = *(const uint2*)&sB[(r0 + 8)*BST + ko + 8];
                ap[mt][0] = prmt(L00.x, L00.y, 0x5410u); ar[mt][0] = prmt(L00.x, L00.y, 0x7632u);
                ap[mt][1] = prmt(L10.x, L10.y, 0x5410u); ar[mt][1] = prmt(L10.x, L10.y, 0x7632u);
                ap[mt][2] = prmt(L08.x, L08.y, 0x5410u); ar[mt][2] = prmt(L08.x, L08.y, 0x7632u);
                ap[mt][3] = prmt(L18.x, L18.y, 0x5410u); ar[mt][3] = prmt(L18.x, L18.y, 0x7632u);
            }
#pragma unroll
            for (int nt = 0; nt < 3; nt++) {
                int n = nt*8 + g;
                unsigned bp0 = sEp[n*ESTT + xp0];
                unsigned bp1 = sEp[n*ESTT + xp0 + 4];
                unsigned br0 = sEr[n*ESTT + xp0];
                unsigned br1 = sEr[n*ESTT + xp0 + 4];
#pragma unroll
                for (int mt = 0; mt < 2; mt++) {
                    mma16(d[mt][nt], ap[mt][0], ap[mt][1], ap[mt][2], ap[mt][3], bp0, bp1);
                    mma16(d[mt][nt], ap[mt][0], ap[mt][1], ap[mt][2], ap[mt][3], br0, br1);
                    mma16(d[mt][nt], ar[mt][0], ar[mt][1], ar[mt][2], ar[mt][3], bp0, bp1);
                }
            }
        }
        __syncthreads();
    }

    float2* sXw = (float2*)(s_pool + OFF_B0);
    float2* stw = (float2*)(s_pool + 12992);
#pragma unroll
    for (int mt = 0; mt < 2; mt++) {
        int r0 = wid*32 + mt*16 + g;
#pragma unroll
        for (int nt = 0; nt < 3; nt++) {
            int kx = nt*4 + t4;
            sXw[ r0     *13 + kx] = make_float2(d[mt][nt][0], d[mt][nt][1]);
            sXw[(r0 + 8)*13 + kx] = make_float2(d[mt][nt][2], d[mt][nt][3]);
        }
    }
    stw[tid] = g_tw[tid];
    __syncthreads();

    for (int cell = tid; cell < 288; cell += 256) {
        int kyi = cell / 12, kx = cell % 12;
        int ky  = (kyi < 12) ? kyi : (kyi + 232);
        float ar2 = 0.f, ai2 = 0.f;
        for (int y = 0; y < 256; y++) {
            float2 a = sXw[y*13 + kx];
            float2 w = stw[(ky*y) & 255];
            ar2 += a.x*w.x + a.y*w.y;
            ai2 += a.y*w.x - a.x*w.y;
        }
        g_xf[(size_t)bc*288 + cell] = make_float2(ar2, ai2);
    }
}

// ---------------- mode mixing ----------------
__global__ void k_mix(int l) {
    __shared__ float2 sxf[4][64];
    int b = blockIdx.x / 72, grp = blockIdx.x % 72;
    int cell0 = grp * 4;
    {
        int c = threadIdx.x >> 6, i = threadIdx.x & 63;
        sxf[c][i] = g_xf[((size_t)b*CC + i)*288 + cell0 + c];
    }
    __syncthreads();
    int cc = threadIdx.x >> 6, o = threadIdx.x & 63;
    int cell = cell0 + cc;
    int kyi = cell / 12, kx = cell % 12;
    const float2* wp = g_wt + (((size_t)l*NKY + kyi)*12 + kx)*4096 + o;
    float ar = 0.f, ai = 0.f;
#pragma unroll 8
    for (int i = 0; i < 64; i++) {
        float2 a = sxf[cc][i];
        float2 w = wp[(size_t)i * 64];
        ar += a.x*w.x - a.y*w.y;
        ai += a.x*w.y + a.y*w.x;
    }
    g_yf[((size_t)b*CC + o)*288 + cell] = make_float2(ar, ai);
}

// ---------------- inverse H ----------------
__global__ void k_inv_h() {
    __shared__ float2 sy[288];
    __shared__ float2 tw[256];
    int bo = blockIdx.x;
    for (int t = threadIdx.x; t < 256; t += 256) tw[t] = g_tw[t];
    for (int t = threadIdx.x; t < 288; t += 256) sy[t] = g_yf[(size_t)bo*288 + t];
    __syncthreads();
    int y = threadIdx.x;
    float2 acc[12];
#pragma unroll
    for (int kx = 0; kx < 12; kx++) acc[kx] = make_float2(0.f, 0.f);
    for (int kyi = 0; kyi < 24; kyi++) {
        int ky = (kyi < 12) ? kyi : (kyi + 232);
        float2 w = tw[(ky*y) & 255];
#pragma unroll
        for (int kx = 0; kx < 12; kx++) {
            float2 a = sy[kyi*12 + kx];
            acc[kx].x += a.x*w.x - a.y*w.y;
            acc[kx].y += a.x*w.y + a.y*w.x;
        }
    }
#pragma unroll
    for (int kx = 0; kx < 12; kx++)
        g_g[((size_t)bo*256 + y)*12 + kx] = acc[kx];
}

// ---------------- fused combine: pre-paired planes, uniform K=88 ----------------
#define APR 44
#define BPR 72
#define XP 68
__global__ void __launch_bounds__(256) k_combine(const float* __restrict__ pw_b, int l) {
    const unsigned* hin = (l & 1) ? g_hPB : g_hPA;
    unsigned* hpout = (l & 1) ? g_hPA : g_hPB;
    __shared__ __align__(16) unsigned sAp[64*APR];
    __shared__ __align__(16) unsigned sAr[64*APR];
    __shared__ __align__(16) unsigned sBp[44*BPR];
    __shared__ __align__(16) unsigned sBr[44*BPR];
    __shared__ __align__(16) float    sD[64*XP];
    __shared__ float  sbias[64];

    int y = blockIdx.x & 255;
    int b = blockIdx.x >> 8;
    int tid = threadIdx.x;

#pragma unroll
    for (int it = 0; it < 2; it++) {
        int t = it*256 + tid;
        int o = t >> 3, q = t & 7;
        *(uint4*)&sAp[o*APR + q*4] = *(const uint4*)(g_pwpP + (l*64 + o)*32 + q*4);
        *(uint4*)&sAr[o*APR + q*4] = *(const uint4*)(g_pwpR + (l*64 + o)*32 + q*4);
    }
#pragma unroll
    for (int it = 0; it < 2; it++) {
        int t = it*256 + tid;
        if (t < 384) {
            int o = t / 6, j2 = t % 6;
            float4 gq = *(const float4*)(g_g + (((size_t)b*64 + o)*256 + y)*12 + 2*j2);
            unsigned sr0 = split2(gq.x), si0 = split2(gq.y);
            unsigned sr1 = split2(gq.z), si1 = split2(gq.w);
            sAp[o*APR + 32 + j2] = prmt(sr0, sr1, 0x5410u);
            sAr[o*APR + 32 + j2] = prmt(sr0, sr1, 0x7632u);
            sAp[o*APR + 38 + j2] = prmt(si0, si1, 0x5410u);
            sAr[o*APR + 38 + j2] = prmt(si0, si1, 0x7632u);
        }
    }
    if (tid < 64) sbias[tid] = pw_b[l*64 + tid];

    int wid = tid >> 5, lane = tid & 31;
    int mt = wid & 3, nh = wid >> 2;
    int g = lane >> 2, t4 = lane & 3;

    uint4 pf[4];
#pragma unroll
    for (int it = 0; it < 2; it++) {
        int s = it*256 + tid;
        int p = s >> 4, q = s & 15;
        size_t rb = (((size_t)b*64 + 2*p)*256 + y) << 8;
        pf[2*it    ] = *(const uint4*)(hin + rb + q*4);
        pf[2*it + 1] = *(const uint4*)(hin + rb + 65536 + q*4);
    }

#pragma unroll 1
    for (int xc = 0; xc < 4; xc++) {
        int x0 = xc << 6;
#pragma unroll
        for (int it = 0; it < 2; it++) {
            int s = it*256 + tid;
            int p = s >> 4, q = s & 15;
            uint4 u = pf[2*it], v = pf[2*it + 1];
            uint4 P, R;
            P.x = prmt(u.x, v.x, 0x5410u); R.x = prmt(u.x, v.x, 0x7632u);
            P.y = prmt(u.y, v.y, 0x5410u); R.y = prmt(u.y, v.y, 0x7632u);
            P.z = prmt(u.z, v.z, 0x5410u); R.z = prmt(u.z, v.z, 0x7632u);
            P.w = prmt(u.w, v.w, 0x5410u); R.w = prmt(u.w, v.w, 0x7632u);
            *(uint4*)&sBp[p*BPR + q*4] = P;
            *(uint4*)&sBr[p*BPR + q*4] = R;
        }
        if (tid < 192) {
            int e2 = tid >> 4, q = tid & 15;
            *(uint4*)&sBp[(32 + e2)*BPR + q*4] = *(const uint4*)(g_EIpP + e2*256 + x0 + q*4);
            *(uint4*)&sBr[(32 + e2)*BPR + q*4] = *(const uint4*)(g_EIpR + e2*256 + x0 + q*4);
        }
        __syncthreads();
        if (xc < 3) {
#pragma unroll
            for (int it = 0; it < 2; it++) {
                int s = it*256 + tid;
                int p = s >> 4, q = s & 15;
                size_t rb = (((size_t)b*64 + 2*p)*256 + y) << 8;
                pf[2*it    ] = *(const uint4*)(hin + rb + x0 + 64 + q*4);
                pf[2*it + 1] = *(const uint4*)(hin + rb + 65536 + x0 + 64 + q*4);
            }
        }

        float d[4][4];
#pragma unroll
        for (int nt = 0; nt < 4; nt++)
#pragma unroll
            for (int r = 0; r < 4; r++) d[nt][r] = 0.f;

#pragma unroll
        for (int kt = 0; kt < 5; kt++) {
            int kp = kt*8 + t4;
            int ra = (mt*16 + g)*APR, rb2 = (mt*16 + g + 8)*APR;
            unsigned ap0 = sAp[ra  + kp], ap2 = sAp[ra  + kp + 4];
            unsigned ap1 = sAp[rb2 + kp], ap3 = sAp[rb2 + kp + 4];
            unsigned ar0 = sAr[ra  + kp], ar2 = sAr[ra  + kp + 4];
            unsigned ar1 = sAr[rb2 + kp], ar3 = sAr[rb2 + kp + 4];
#pragma unroll
            for (int nt = 0; nt < 4; nt++) {
                int xl = nh*32 + nt*8 + g;
                unsigned bp0 = sBp[ kp      *BPR + xl];
                unsigned bp1 = sBp[(kp + 4) *BPR + xl];
                unsigned br0 = sBr[ kp      *BPR + xl];
                unsigned br1 = sBr[(kp + 4) *BPR + xl];
                mma16(d[nt], ap0, ap1, ap2, ap3, bp0, bp1);
                mma16(d[nt], ap0, ap1, ap2, ap3, br0, br1);
                mma16(d[nt], ar0, ar1, ar2, ar3, bp0, bp1);
            }
        }
        {
            int kp = 40 + t4;
            unsigned ap0 = sAp[(mt*16 + g    )*APR + kp];
            unsigned ap1 = sAp[(mt*16 + g + 8)*APR + kp];
            unsigned ar0 = sAr[(mt*16 + g    )*APR + kp];
            unsigned ar1 = sAr[(mt*16 + g + 8)*APR + kp];
#pragma unroll
            for (int nt = 0; nt < 4; nt++) {
                int xl = nh*32 + nt*8 + g;
                unsigned bp = sBp[kp*BPR + xl];
                unsigned br = sBr[kp*BPR + xl];
                mma_bf16(d[nt], ap0, ap1, bp);
                mma_bf16(d[nt], ap0, ap1, br);
                mma_bf16(d[nt], ar0, ar1, bp);
            }
        }

#pragma unroll
        for (int nt = 0; nt < 4; nt++) {
            int xl = nh*32 + nt*8 + 2*t4;
            int o0 = mt*16 + g;
            *(float2*)&sD[ o0      * XP + xl] = make_float2(d[nt][0], d[nt][1]);
            *(float2*)&sD[(o0 + 8) * XP + xl] = make_float2(d[nt][2], d[nt][3]);
        }
        __syncthreads();

#pragma unroll
        for (int it = 0; it < 4; it++) {
            int o  = it*16 + (tid >> 4);
            int x4 = tid & 15;
            float4 v = *(float4*)&sD[o*XP + x4*4];
            float bias = sbias[o];
            size_t base = ((((size_t)b*64 + o)*256 + y) << 8) + x0 + x4*4;
            float u0 = v.x + bias, u1 = v.y + bias, u2 = v.z + bias, u3 = v.w + bias;
            if (l < 3) {
                u0 = gelu_e(u0); u1 = gelu_e(u1); u2 = gelu_e(u2); u3 = gelu_e(u3);
            }
            uint4 up;
            up.x = split2(u0); up.y = split2(u1); up.z = split2(u2); up.w = split2(u3);
            *(uint4*)(hpout + base) = up;
        }
        __syncthreads();
    }
}

// ---------------- final: packed-input fc1 (k16) + gelu + fc2 ----------------
#define FSP 136
__global__ void __launch_bounds__(256) k_final(const float* __restrict__ b1,
                        const float* __restrict__ w2, const float* __restrict__ b2,
                        float* __restrict__ out) {
    __shared__ __align__(16) unsigned sHp[32*FSP];
    __shared__ __align__(16) unsigned sHr[32*FSP];
    __shared__ __align__(16) unsigned sWp[32*FSP];
    __shared__ __align__(16) unsigned sWr[32*FSP];
    __shared__ float sb1[FCH];
    __shared__ float sw2[FCH];
    int xh = blockIdx.x & 1;
    int y  = (blockIdx.x >> 1) & 255;
    int b  = blockIdx.x >> 9;
    int tid = threadIdx.x;
    int x0 = xh << 7;

    // h pairs along c (input is layer-3 split-packed output in g_hPA)
#pragma unroll
    for (int it = 0; it < 4; it++) {
        int s = it*256 + tid;
        int c2 = s >> 5, q = s & 31;
        size_t rb = (((size_t)b*64 + 2*c2)*256 + y) << 8;
        uint4 ua = *(const uint4*)(g_hPA + rb + x0 + q*4);
        uint4 ub = *(const uint4*)(g_hPA + rb + 65536 + x0 + q*4);
        uint4 P, R;
        P.x = prmt(ua.x, ub.x, 0x5410u); R.x = prmt(ua.x, ub.x, 0x7632u);
        P.y = prmt(ua.y, ub.y, 0x5410u); R.y = prmt(ua.y, ub.y, 0x7632u);
        P.z = prmt(ua.z, ub.z, 0x5410u); R.z = prmt(ua.z, ub.z, 0x7632u);
        P.w = prmt(ua.w, ub.w, 0x5410u); R.w = prmt(ua.w, ub.w, 0x7632u);
        *(uint4*)&sHp[c2*FSP + q*4] = P;
        *(uint4*)&sHr[c2*FSP + q*4] = R;
    }
#pragma unroll
    for (int it = 0; it < 4; it++) {
        int s = it*256 + tid;
        int c2 = s >> 5, q = s & 31;
        *(uint4*)&sWp[c2*FSP + q*4] = ((const uint4*)g_w1pP)[c2*32 + q];
        *(uint4*)&sWr[c2*FSP + q*4] = ((const uint4*)g_w1pR)[c2*32 + q];
    }
    if (tid < 128) { sb1[tid] = b1[tid]; sw2[tid] = w2[tid]; }
    __syncthreads();

    int wid = tid >> 5, lane = tid & 31;
    int g = lane >> 2, t4 = lane & 3;
    float d[16][4];
#pragma unroll
    for (int nt = 0; nt < 16; nt++)
#pragma unroll
        for (int r = 0; r < 4; r++) d[nt][r] = 0.f;

#pragma unroll
    for (int kt = 0; kt < 4; kt++) {
        int kp = kt*8 + t4;
        int X0 = wid*16 + g;
        unsigned ap0 = sHp[ kp     *FSP + X0], ap1 = sHp[ kp     *FSP + X0 + 8];
        unsigned ap2 = sHp[(kp + 4)*FSP + X0], ap3 = sHp[(kp + 4)*FSP + X0 + 8];
        unsigned ar0 = sHr[ kp     *FSP + X0], ar1 = sHr[ kp     *FSP + X0 + 8];
        unsigned ar2 = sHr[(kp + 4)*FSP + X0], ar3 = sHr[(kp + 4)*FSP + X0 + 8];
#pragma unroll
        for (int nt = 0; nt < 16; nt++) {
            int n = nt*8 + g;
            unsigned bp0 = sWp[ kp     *FSP + n];
            unsigned bp1 = sWp[(kp + 4)*FSP + n];
            unsigned br0 = sWr[ kp     *FSP + n];
            unsigned br1 = sWr[(kp + 4)*FSP + n];
            mma16(d[nt], ap0, ap1, ap2, ap3, bp0, bp1);
            mma16(d[nt], ap0, ap1, ap2, ap3, br0, br1);
            mma16(d[nt], ar0, ar1, ar2, ar3, bp0, bp1);
        }
    }

    float pA = 0.f, pB = 0.f;
#pragma unroll
    for (int nt = 0; nt < 16; nt++) {
        int d0 = nt*8 + 2*t4, d1 = d0 + 1;
        float bb0 = sb1[d0], bb1 = sb1[d1];
        float ww0 = sw2[d0], ww1 = sw2[d1];
        pA += gelu_e(d[nt][0] + bb0) * ww0;
        pA += gelu_e(d[nt][1] + bb1) * ww1;
        pB += gelu_e(d[nt][2] + bb0) * ww0;
        pB += gelu_e(d[nt][3] + bb1) * ww1;
    }
    pA += __shfl_xor_sync(0xffffffffu, pA, 1);
    pA += __shfl_xor_sync(0xffffffffu, pA, 2);
    pB += __shfl_xor_sync(0xffffffffu, pB, 1);
    pB += __shfl_xor_sync(0xffffffffu, pB, 2);
    if (t4 == 0) {
        float bias2 = b2[0];
        size_t base = ((size_t)b*256 + y)*256 + x0 + wid*16 + g;
        out[base    ] = pA + bias2;
        out[base + 8] = pB + bias2;
    }
}

// ---------------- launcher ----------------
extern "C" void kernel_launch(void* const* d_in, const int* in_sizes, int n_in,
                              void* d_out, int out_size) {
    const float* x     = (const float*)d_in[0];
    const float* fc0_w = (const float*)d_in[1];
    const float* fc0_b = (const float*)d_in[2];
    const float* sc_w  = (const float*)d_in[3];
    const float* pw_w  = (const float*)d_in[4];
    const float* pw_b  = (const float*)d_in[5];
    const float* fc1_w = (const float*)d_in[6];
    const float* fc1_b = (const float*)d_in[7];
    const float* fc2_w = (const float*)d_in[8];
    const float* fc2_b = (const float*)d_in[9];
    float* out = (float*)d_out;

    k_E<<<1, 256>>>();
    k_tw<<<1, 256>>>();
    k_lift<<<65536, 256>>>(x, fc0_w, fc0_b);
    k_fwd<<<1024, 256>>>(0);
    k_wt<<<18432, 256>>>(sc_w);
    k_pws<<<32, 256>>>(pw_w);
    k_w1p<<<16, 256>>>(fc1_w);
    k_mix<<<1152, 256>>>(0);
    k_inv_h<<<1024, 256>>>();
    k_combine<<<4096, 256>>>(pw_b, 0);
    for (int l = 1; l < 4; l++) {
        k_fwd<<<1024, 256>>>(l);
        k_mix<<<1152, 256>>>(l);
        k_inv_h<<<1024, 256>>>();
        k_combine<<<4096, 256>>>(pw_b, l);
    }
    k_final<<<8192, 256>>>(fc1_b, fc2_w, fc2_b, out);
}